// round 2
// baseline (speedup 1.0000x reference)
#include <cuda_runtime.h>
#include <cuda_bf16.h>

// ---------------- problem constants ----------------
#define B     512
#define C_IN  12
#define T_IN  5000
#define T1    496      // (5000-50)/10+1
#define T2    95       // (496-25)/5+1
#define NF    32
#define LAT   32
#define HID   64
#define EPSV  1e-5f

typedef unsigned long long ull;

// packed fp32x2 FMA: d = a*b + d  (elementwise on two packed fp32) — bit-exact fp32
#define FMA2(d, a, b) asm("fma.rn.f32x2 %0, %1, %2, %0;" : "+l"(d) : "l"(a), "l"(b))

// ---------------- scratch (static device memory; no allocation) ----------------
__device__ float g_y1[B * 32 * T1];        // conv1 raw output [b][oc][t]  (no bias; cancels in BN)
__device__ float g_y2t[B * T2 * NF];       // conv2 raw output TRANSPOSED [b][t][f]
__device__ float g_xt[B * T2 * LAT];       // post proj+LN [b][t][l]
__device__ float g_stats1[64];             // sum[32], sumsq[32]
__device__ float g_stats2[64];
__device__ float g_s1[32], g_sh1[32];      // BN1 scale/shift
__device__ float g_s2[32], g_sh2[32];      // BN2 scale/shift

// ---------------- init: zero stats ----------------
__global__ void init_kernel() {
    int i = threadIdx.x;
    if (i < 64) { g_stats1[i] = 0.f; g_stats2[i] = 0.f; }
}

// ---------------- conv1 + BN1 stats (fp32x2 packed) ----------------
// grid (8, 512): x = t-tile (64 outputs), y = batch. 64 threads (2 warps).
// thread tile: 8 oc (4 float2 pairs) x 4 t (t = tg + 16*i).
// ocg = tid>>4 (0..3) -> oc0 = ocg*8 ; tg = tid&15.
__global__ void conv1_kernel(const float* __restrict__ x,
                             const float* __restrict__ w1) {
    __shared__ __align__(16) float  xs_raw[680];        // raw input segment
    __shared__ __align__(16) float2 xs2d[50 * 64];      // [k][t] duplicated (v,v)
    __shared__ __align__(16) float  ws2[50 * 34];       // [k][oc] stride 34 (bank spread, 8B-aligned rows)
    __shared__ float s_sum[32], s_sq[32];

    const int b   = blockIdx.y;
    const int t0  = blockIdx.x * 64;
    const int tid = threadIdx.x;
    const int ocg = tid >> 4;
    const int tg  = tid & 15;

    if (tid < 32) { s_sum[tid] = 0.f; s_sq[tid] = 0.f; }

    ull acc[4][4];
#pragma unroll
    for (int p = 0; p < 4; p++)
#pragma unroll
        for (int i = 0; i < 4; i++) acc[p][i] = 0ull;

    for (int c = 0; c < C_IN; c++) {
        __syncthreads();
        // stage raw input (coalesced), zero-pad past end
        {
            const float* xrow = x + (b * C_IN + c) * T_IN + t0 * 10;
            const int lim = T_IN - t0 * 10;
            for (int s = tid; s < 680; s += 64)
                xs_raw[s] = (s < lim) ? xrow[s] : 0.f;
        }
        __syncthreads();
        // build k-transposed duplicated x tile + transposed weights
        for (int idx = tid; idx < 3200; idx += 64) {
            int k = idx >> 6, t = idx & 63;
            float v = xs_raw[t * 10 + k];
            xs2d[idx] = make_float2(v, v);
        }
        for (int idx = tid; idx < 1600; idx += 64) {
            int oc = idx / 50, k = idx - oc * 50;
            ws2[k * 34 + oc] = w1[oc * (C_IN * 50) + c * 50 + k];
        }
        __syncthreads();

#pragma unroll 5
        for (int k = 0; k < 50; k++) {
            ull wv[4], xv[4];
#pragma unroll
            for (int p = 0; p < 4; p++)
                wv[p] = *(const ull*)&ws2[k * 34 + ocg * 8 + 2 * p];
#pragma unroll
            for (int i = 0; i < 4; i++)
                xv[i] = *(const ull*)&xs2d[k * 64 + tg + 16 * i];
#pragma unroll
            for (int p = 0; p < 4; p++)
#pragma unroll
                for (int i = 0; i < 4; i++)
                    FMA2(acc[p][i], wv[p], xv[i]);
        }
    }
    __syncthreads();

    float psum[8], psq[8];
#pragma unroll
    for (int j = 0; j < 8; j++) { psum[j] = 0.f; psq[j] = 0.f; }

#pragma unroll
    for (int i = 0; i < 4; i++) {
        int t = t0 + tg + 16 * i;
        if (t < T1) {
#pragma unroll
            for (int p = 0; p < 4; p++) {
                float2 v = *(float2*)&acc[p][i];
                int oc = ocg * 8 + 2 * p;
                g_y1[(b * 32 + oc    ) * T1 + t] = v.x;
                g_y1[(b * 32 + oc + 1) * T1 + t] = v.y;
                psum[2*p]   += v.x;  psq[2*p]   += v.x * v.x;
                psum[2*p+1] += v.y;  psq[2*p+1] += v.y * v.y;
            }
        }
    }
#pragma unroll
    for (int j = 0; j < 8; j++) {
        atomicAdd(&s_sum[ocg * 8 + j], psum[j]);
        atomicAdd(&s_sq [ocg * 8 + j], psq[j]);
    }
    __syncthreads();
    if (tid < 32) {
        atomicAdd(&g_stats1[tid],      s_sum[tid]);
        atomicAdd(&g_stats1[32 + tid], s_sq[tid]);
    }
}

// ---------------- BN finalize (which: 0 -> BN1, 1 -> BN2) ----------------
__global__ void finalize_kernel(int which,
                                const float* __restrict__ g,
                                const float* __restrict__ bb) {
    int c = threadIdx.x;
    if (c >= 32) return;
    const float* st = which ? g_stats2 : g_stats1;
    float nInv = which ? (1.f / (float)(B * T2)) : (1.f / (float)(B * T1));
    float mean = st[c] * nInv;
    float var  = st[32 + c] * nInv - mean * mean;
    float s    = g[c] * rsqrtf(var + EPSV);
    if (which) { g_s2[c] = s; g_sh2[c] = bb[c] - mean * s; }
    else       { g_s1[c] = s; g_sh1[c] = bb[c] - mean * s; }
}

// ---------------- conv2 (BN1+relu on the fly) + BN2 stats (fp32x2) ----------------
// grid (2, 512): x = t2-half (48 outputs), y = batch. 64 threads.
// thread tile: 8 oc (4 pairs) x 3 t2 (t = tg + 16*i, i<3).
__global__ void conv2_kernel(const float* __restrict__ w2) {
    __shared__ __align__(16) float  zraw[260];          // bn1+relu'd y1 segment
    __shared__ __align__(16) float2 zs2d[25 * 48];      // [k][t] duplicated
    __shared__ __align__(16) float  ws2[25 * 34];       // [k][oc] stride 34
    __shared__ float s_sum[32], s_sq[32];

    const int b    = blockIdx.y;
    const int base = blockIdx.x * 48;
    const int tid  = threadIdx.x;
    const int ocg  = tid >> 4;
    const int tg   = tid & 15;

    if (tid < 32) { s_sum[tid] = 0.f; s_sq[tid] = 0.f; }

    ull acc[4][3];
#pragma unroll
    for (int p = 0; p < 4; p++)
#pragma unroll
        for (int i = 0; i < 3; i++) acc[p][i] = 0ull;

    for (int c = 0; c < 32; c++) {
        __syncthreads();
        {
            const float sc = g_s1[c], sh = g_sh1[c];
            const float* yrow = g_y1 + (b * 32 + c) * T1;
            const int g0 = base * 5;
            for (int s = tid; s < 260; s += 64) {
                int gidx = g0 + s;
                float v = (gidx < T1) ? fmaf(yrow[gidx], sc, sh) : 0.f;
                zraw[s] = fmaxf(v, 0.f);
            }
        }
        __syncthreads();
        for (int idx = tid; idx < 1200; idx += 64) {
            int k = idx / 48, t = idx - k * 48;
            float v = (base + t < T2) ? zraw[5 * t + k] : 0.f;
            zs2d[idx] = make_float2(v, v);
        }
        for (int idx = tid; idx < 800; idx += 64) {
            int oc = idx / 25, k = idx - oc * 25;
            ws2[k * 34 + oc] = w2[oc * (32 * 25) + c * 25 + k];
        }
        __syncthreads();

#pragma unroll 5
        for (int k = 0; k < 25; k++) {
            ull wv[4], xv[3];
#pragma unroll
            for (int p = 0; p < 4; p++)
                wv[p] = *(const ull*)&ws2[k * 34 + ocg * 8 + 2 * p];
#pragma unroll
            for (int i = 0; i < 3; i++)
                xv[i] = *(const ull*)&zs2d[k * 48 + tg + 16 * i];
#pragma unroll
            for (int p = 0; p < 4; p++)
#pragma unroll
                for (int i = 0; i < 3; i++)
                    FMA2(acc[p][i], wv[p], xv[i]);
        }
    }
    __syncthreads();

    float psum[8], psq[8];
#pragma unroll
    for (int j = 0; j < 8; j++) { psum[j] = 0.f; psq[j] = 0.f; }

#pragma unroll
    for (int i = 0; i < 3; i++) {
        int t = base + tg + 16 * i;
        if (t < T2) {
#pragma unroll
            for (int p = 0; p < 4; p++) {
                float2 v = *(float2*)&acc[p][i];
                int oc = ocg * 8 + 2 * p;
                g_y2t[(b * T2 + t) * NF + oc    ] = v.x;   // transposed store
                g_y2t[(b * T2 + t) * NF + oc + 1] = v.y;
                psum[2*p]   += v.x;  psq[2*p]   += v.x * v.x;
                psum[2*p+1] += v.y;  psq[2*p+1] += v.y * v.y;
            }
        }
    }
#pragma unroll
    for (int j = 0; j < 8; j++) {
        atomicAdd(&s_sum[ocg * 8 + j], psum[j]);
        atomicAdd(&s_sq [ocg * 8 + j], psq[j]);
    }
    __syncthreads();
    if (tid < 32) {
        atomicAdd(&g_stats2[tid],      s_sum[tid]);
        atomicAdd(&g_stats2[32 + tid], s_sq[tid]);
    }
}

// ---------------- projection + layernorm ----------------
// warp per (b,t) token
__global__ void projln_kernel(const float* __restrict__ pw,
                              const float* __restrict__ pb,
                              const float* __restrict__ lng,
                              const float* __restrict__ lnb) {
    __shared__ float pws[32 * 33];   // pws[f*33 + l] = pw[l*32 + f]
    const int tid = threadIdx.x;
    for (int idx = tid; idx < 1024; idx += blockDim.x)
        pws[(idx & 31) * 33 + (idx >> 5)] = pw[idx];
    __syncthreads();

    const int lane   = tid & 31;
    const int warpId = (blockIdx.x * blockDim.x + tid) >> 5;
    const int nw     = (gridDim.x * blockDim.x) >> 5;

    const float s2  = g_s2[lane], sh2 = g_sh2[lane];
    const float pbv = pb[lane];
    const float lg  = lng[lane], lb = lnb[lane];

    for (int task = warpId; task < B * T2; task += nw) {
        float v = g_y2t[task * NF + lane];
        v = fmaf(v, s2, sh2);
        v = v > 0.f ? v : 0.f;

        float a = pbv;
#pragma unroll
        for (int f = 0; f < 32; f++)
            a = fmaf(__shfl_sync(0xffffffffu, v, f), pws[f * 33 + lane], a);

        // layernorm across the 32 lanes
        float s = a;
#pragma unroll
        for (int off = 16; off > 0; off >>= 1) s += __shfl_xor_sync(0xffffffffu, s, off);
        float mean = s * (1.f / 32.f);
        float d = a - mean;
        float q = d * d;
#pragma unroll
        for (int off = 16; off > 0; off >>= 1) q += __shfl_xor_sync(0xffffffffu, q, off);
        float var = q * (1.f / 32.f);
        g_xt[task * LAT + lane] = fmaf(d * rsqrtf(var + EPSV), lg, lb);
    }
}

// ---------------- PLRNN scan + pool + output projection ----------------
// warp per batch row. grid 64 x 256 threads = 512 warps.
__global__ void recur_kernel(const float* __restrict__ Ain,
                             const float* __restrict__ Win,
                             const float* __restrict__ hbin,
                             const float* __restrict__ owin,
                             const float* __restrict__ obin,
                             float* __restrict__ out) {
    __shared__ float As[32 * 33];    // A[l][m] at As[l*33+m]
    __shared__ float Ws[32 * 65];    // W[m][j] at Ws[m*65+j]
    __shared__ float ows[32 * 33];   // out_w[l][m] at ows[l*33+m]
    __shared__ float hbs[64];

    const int tid = threadIdx.x;
    for (int idx = tid; idx < 1024; idx += 256) {
        As[(idx >> 5) * 33 + (idx & 31)]  = Ain[idx];
        ows[(idx >> 5) * 33 + (idx & 31)] = owin[idx];
    }
    for (int idx = tid; idx < 2048; idx += 256)
        Ws[(idx >> 6) * 65 + (idx & 63)] = Win[idx];
    if (tid < 64) hbs[tid] = hbin[tid];
    __syncthreads();

    const int lane = tid & 31;
    const int b    = blockIdx.x * 8 + (tid >> 5);

    float h = 0.f, sum = 0.f;
    const float* xrow = g_xt + b * T2 * LAT + lane;

    for (int t = 0; t < T2; t++) {
        float xv = xrow[t * LAT];
        float lin = 0.f;
        float p0 = hbs[lane];
        float p1 = hbs[32 + lane];
#pragma unroll
        for (int m = 0; m < 32; m++) {
            float hm = __shfl_sync(0xffffffffu, h, m);
            lin = fmaf(As[lane * 33 + m],      hm, lin);
            p0  = fmaf(Ws[m * 65 + lane],      hm, p0);
            p1  = fmaf(Ws[m * 65 + 32 + lane], hm, p1);
        }
        float r0 = fmaxf(p0, 0.f);
        float r1 = fmaxf(p1, 0.f);
        float nl = 0.f;
#pragma unroll
        for (int j = 0; j < 32; j++)
            nl = fmaf(__shfl_sync(0xffffffffu, r0, j), Ws[lane * 65 + j], nl);
#pragma unroll
        for (int j = 0; j < 32; j++)
            nl = fmaf(__shfl_sync(0xffffffffu, r1, j), Ws[lane * 65 + 32 + j], nl);

        h = lin + nl + xv;
        sum += h;
    }

    float pooled = sum * (1.f / (float)T2);
    float o = obin[lane];
#pragma unroll
    for (int m = 0; m < 32; m++)
        o = fmaf(ows[lane * 33 + m], __shfl_sync(0xffffffffu, pooled, m), o);
    out[b * 32 + lane] = o;
}

// ---------------- launcher ----------------
extern "C" void kernel_launch(void* const* d_in, const int* in_sizes, int n_in,
                              void* d_out, int out_size) {
    const float* x       = (const float*)d_in[0];
    const float* conv1_w = (const float*)d_in[1];
    const float* bn1_g   = (const float*)d_in[3];
    const float* bn1_b   = (const float*)d_in[4];
    const float* conv2_w = (const float*)d_in[5];
    const float* bn2_g   = (const float*)d_in[7];
    const float* bn2_b   = (const float*)d_in[8];
    const float* proj_w  = (const float*)d_in[9];
    const float* proj_b  = (const float*)d_in[10];
    const float* ln_g    = (const float*)d_in[11];
    const float* ln_b    = (const float*)d_in[12];
    const float* A       = (const float*)d_in[13];
    const float* W       = (const float*)d_in[14];
    const float* h_bias  = (const float*)d_in[15];
    const float* out_w   = (const float*)d_in[16];
    const float* out_b   = (const float*)d_in[17];
    float* out = (float*)d_out;

    init_kernel<<<1, 64>>>();
    conv1_kernel<<<dim3(8, B), 64>>>(x, conv1_w);
    finalize_kernel<<<1, 32>>>(0, bn1_g, bn1_b);
    conv2_kernel<<<dim3(2, B), 64>>>(conv2_w);
    finalize_kernel<<<1, 32>>>(1, bn2_g, bn2_b);
    projln_kernel<<<512, 256>>>(proj_w, proj_b, ln_g, ln_b);
    recur_kernel<<<64, 256>>>(A, W, h_bias, out_w, out_b, out);
}

// round 3
// speedup vs baseline: 1.1224x; 1.1224x over previous
#include <cuda_runtime.h>
#include <cuda_bf16.h>

// ---------------- problem constants ----------------
#define B     512
#define C_IN  12
#define T_IN  5000
#define T1    496      // (5000-50)/10+1
#define T2    95       // (496-25)/5+1
#define NF    32
#define LAT   32
#define HID   64
#define EPSV  1e-5f

typedef unsigned long long ull;

// packed fp32x2 FMA: d = a*b + d (elementwise, bit-exact fp32 per lane)
#define FMA2(d, a, b) asm("fma.rn.f32x2 %0, %1, %2, %0;" : "+l"(d) : "l"(a), "l"(b))

// ---------------- scratch (static device memory; no allocation) ----------------
__device__ float g_y1[B * 32 * T1];        // conv1 raw output [b][oc][t] (bias folded into BN)
__device__ float g_y2t[B * T2 * NF];       // conv2 raw output TRANSPOSED [b][t][f]
__device__ float g_xt[B * T2 * LAT];       // post proj+LN [b][t][l]
__device__ float g_stats1[64];             // sum[32], sumsq[32]
__device__ float g_stats2[64];
__device__ float g_s1[32], g_sh1[32];      // BN1 scale/shift
__device__ float g_s2[32], g_sh2[32];      // BN2 scale/shift

// ---------------- init: zero stats ----------------
__global__ void init_kernel() {
    int i = threadIdx.x;
    if (i < 64) { g_stats1[i] = 0.f; g_stats2[i] = 0.f; }
}

// ---------------- conv1 + BN1 stats (fp32x2, k-paired) ----------------
// grid (4, 512): x = t-tile (128 outputs), y = batch. 128 threads.
// og = tid>>5 -> oc0 = og*8 (8 oc); lane = tid&31 -> t = t0 + lane + 32*i (4 t).
__global__ void __launch_bounds__(128) conv1_kernel(const float* __restrict__ x,
                                                    const float* __restrict__ w1) {
    __shared__ __align__(16) float xs[1320];    // raw input segment (127*10+50)
    __shared__ __align__(16) float ws[1600];    // [oc][k] 32x50, k contiguous
    __shared__ float s_sum[32], s_sq[32];

    const int b    = blockIdx.y;
    const int t0   = blockIdx.x * 128;
    const int tid  = threadIdx.x;
    const int og   = tid >> 5;
    const int lane = tid & 31;
    const int oc0  = og * 8;

    if (tid < 32) { s_sum[tid] = 0.f; s_sq[tid] = 0.f; }

    ull acc[8][4];
#pragma unroll
    for (int o = 0; o < 8; o++)
#pragma unroll
        for (int i = 0; i < 4; i++) acc[o][i] = 0ull;

    for (int c = 0; c < C_IN; c++) {
        __syncthreads();
        {
            const float* xrow = x + (b * C_IN + c) * T_IN + t0 * 10;
            const int lim = T_IN - t0 * 10;
            for (int s = tid; s < 1320; s += 128)
                xs[s] = (s < lim) ? xrow[s] : 0.f;
        }
        for (int idx = tid; idx < 1600; idx += 128) {
            int oc = idx / 50, k = idx - oc * 50;
            ws[idx] = w1[oc * (C_IN * 50) + c * 50 + k];
        }
        __syncthreads();

#pragma unroll 5
        for (int kp = 0; kp < 25; kp++) {
            const int k = 2 * kp;
            ull wv[8], xv[4];
#pragma unroll
            for (int o = 0; o < 8; o++)
                wv[o] = *(const ull*)&ws[(oc0 + o) * 50 + k];
#pragma unroll
            for (int i = 0; i < 4; i++)
                xv[i] = *(const ull*)&xs[(lane + 32 * i) * 10 + k];
#pragma unroll
            for (int o = 0; o < 8; o++)
#pragma unroll
                for (int i = 0; i < 4; i++)
                    FMA2(acc[o][i], wv[o], xv[i]);
        }
    }
    __syncthreads();

    float psum[8], psq[8];
#pragma unroll
    for (int o = 0; o < 8; o++) { psum[o] = 0.f; psq[o] = 0.f; }

#pragma unroll
    for (int i = 0; i < 4; i++) {
        int t = t0 + lane + 32 * i;
        if (t < T1) {
#pragma unroll
            for (int o = 0; o < 8; o++) {
                float2 v = *(float2*)&acc[o][i];
                float val = v.x + v.y;
                g_y1[(b * 32 + oc0 + o) * T1 + t] = val;
                psum[o] += val;
                psq[o]  += val * val;
            }
        }
    }
#pragma unroll
    for (int o = 0; o < 8; o++) {
        atomicAdd(&s_sum[oc0 + o], psum[o]);
        atomicAdd(&s_sq [oc0 + o], psq[o]);
    }
    __syncthreads();
    if (tid < 32) {
        atomicAdd(&g_stats1[tid],      s_sum[tid]);
        atomicAdd(&g_stats1[32 + tid], s_sq[tid]);
    }
}

// ---------------- BN finalize (which: 0 -> BN1, 1 -> BN2) ----------------
__global__ void finalize_kernel(int which,
                                const float* __restrict__ g,
                                const float* __restrict__ bb) {
    int c = threadIdx.x;
    if (c >= 32) return;
    const float* st = which ? g_stats2 : g_stats1;
    float nInv = which ? (1.f / (float)(B * T2)) : (1.f / (float)(B * T1));
    float mean = st[c] * nInv;
    float var  = st[32 + c] * nInv - mean * mean;
    float s    = g[c] * rsqrtf(var + EPSV);
    if (which) { g_s2[c] = s; g_sh2[c] = bb[c] - mean * s; }
    else       { g_s1[c] = s; g_sh1[c] = bb[c] - mean * s; }
}

// ---------------- conv2 (BN1+relu on the fly) + BN2 stats (fp32x2, k-paired) ----------------
// grid (2, 512): x = t2 half (48 outputs), y = batch. 128 threads.
// og = tid>>5 -> oc0 = og*8 (8 oc); lane -> t = tbase + lane + 32*i (2 t, guard < 48).
__global__ void __launch_bounds__(128) conv2_kernel(const float* __restrict__ w2) {
    __shared__ __align__(16) float zraw[260];        // bn1+relu'd segment
    __shared__ __align__(16) float zt[64 * 26];      // [t_local][k] padded, zero rows >=48
    __shared__ __align__(16) float ws[32 * 26];      // [oc][k] padded k=25 -> 0
    __shared__ float s_sum[32], s_sq[32];

    const int b     = blockIdx.y;
    const int tbase = blockIdx.x * 48;
    const int tid   = threadIdx.x;
    const int og    = tid >> 5;
    const int lane  = tid & 31;
    const int oc0   = og * 8;

    if (tid < 32) { s_sum[tid] = 0.f; s_sq[tid] = 0.f; }

    ull acc[8][2];
#pragma unroll
    for (int o = 0; o < 8; o++)
#pragma unroll
        for (int i = 0; i < 2; i++) acc[o][i] = 0ull;

    for (int c = 0; c < 32; c++) {
        __syncthreads();
        {
            const float sc = g_s1[c], sh = g_sh1[c];
            const float* yrow = g_y1 + (b * 32 + c) * T1;
            const int g0 = tbase * 5;
            for (int s = tid; s < 260; s += 128) {
                int gi = g0 + s;
                float v = (gi < T1) ? fmaf(yrow[gi], sc, sh) : 0.f;
                zraw[s] = fmaxf(v, 0.f);
            }
        }
        __syncthreads();
        for (int idx = tid; idx < 64 * 26; idx += 128) {
            int tl = idx / 26, k = idx - tl * 26;
            float v = (tl < 48 && k < 25 && (tbase + tl) < T2) ? zraw[tl * 5 + k] : 0.f;
            zt[idx] = v;
        }
        for (int idx = tid; idx < 832; idx += 128) {
            int oc = idx / 26, k = idx - oc * 26;
            ws[idx] = (k < 25) ? w2[oc * (32 * 25) + c * 25 + k] : 0.f;
        }
        __syncthreads();

#pragma unroll
        for (int kp = 0; kp < 13; kp++) {
            const int k = 2 * kp;
            ull wv[8], xv[2];
#pragma unroll
            for (int o = 0; o < 8; o++)
                wv[o] = *(const ull*)&ws[(oc0 + o) * 26 + k];
#pragma unroll
            for (int i = 0; i < 2; i++)
                xv[i] = *(const ull*)&zt[(lane + 32 * i) * 26 + k];
#pragma unroll
            for (int o = 0; o < 8; o++)
#pragma unroll
                for (int i = 0; i < 2; i++)
                    FMA2(acc[o][i], wv[o], xv[i]);
        }
    }
    __syncthreads();

    float psum[8], psq[8];
#pragma unroll
    for (int o = 0; o < 8; o++) { psum[o] = 0.f; psq[o] = 0.f; }

#pragma unroll
    for (int i = 0; i < 2; i++) {
        int tl = lane + 32 * i;
        int t  = tbase + tl;
        if (tl < 48 && t < T2) {
#pragma unroll
            for (int o = 0; o < 8; o++) {
                float2 v = *(float2*)&acc[o][i];
                float val = v.x + v.y;
                g_y2t[(b * T2 + t) * NF + oc0 + o] = val;   // transposed store
                psum[o] += val;
                psq[o]  += val * val;
            }
        }
    }
#pragma unroll
    for (int o = 0; o < 8; o++) {
        atomicAdd(&s_sum[oc0 + o], psum[o]);
        atomicAdd(&s_sq [oc0 + o], psq[o]);
    }
    __syncthreads();
    if (tid < 32) {
        atomicAdd(&g_stats2[tid],      s_sum[tid]);
        atomicAdd(&g_stats2[32 + tid], s_sq[tid]);
    }
}

// ---------------- projection + layernorm ----------------
// warp per (b,t) token
__global__ void projln_kernel(const float* __restrict__ pw,
                              const float* __restrict__ pb,
                              const float* __restrict__ lng,
                              const float* __restrict__ lnb) {
    __shared__ float pws[32 * 33];   // pws[f*33 + l] = pw[l*32 + f]
    const int tid = threadIdx.x;
    for (int idx = tid; idx < 1024; idx += blockDim.x)
        pws[(idx & 31) * 33 + (idx >> 5)] = pw[idx];
    __syncthreads();

    const int lane   = tid & 31;
    const int warpId = (blockIdx.x * blockDim.x + tid) >> 5;
    const int nw     = (gridDim.x * blockDim.x) >> 5;

    const float s2  = g_s2[lane], sh2 = g_sh2[lane];
    const float pbv = pb[lane];
    const float lg  = lng[lane], lb = lnb[lane];

    for (int task = warpId; task < B * T2; task += nw) {
        float v = g_y2t[task * NF + lane];
        v = fmaf(v, s2, sh2);
        v = v > 0.f ? v : 0.f;

        float a = pbv;
#pragma unroll
        for (int f = 0; f < 32; f++)
            a = fmaf(__shfl_sync(0xffffffffu, v, f), pws[f * 33 + lane], a);

        float s = a;
#pragma unroll
        for (int off = 16; off > 0; off >>= 1) s += __shfl_xor_sync(0xffffffffu, s, off);
        float mean = s * (1.f / 32.f);
        float d = a - mean;
        float q = d * d;
#pragma unroll
        for (int off = 16; off > 0; off >>= 1) q += __shfl_xor_sync(0xffffffffu, q, off);
        float var = q * (1.f / 32.f);
        g_xt[task * LAT + lane] = fmaf(d * rsqrtf(var + EPSV), lg, lb);
    }
}

// ---------------- PLRNN scan + pool + output projection ----------------
// warp per batch row. grid 64 x 256 threads = 512 warps.
__global__ void recur_kernel(const float* __restrict__ Ain,
                             const float* __restrict__ Win,
                             const float* __restrict__ hbin,
                             const float* __restrict__ owin,
                             const float* __restrict__ obin,
                             float* __restrict__ out) {
    __shared__ float As[32 * 33];
    __shared__ float Ws[32 * 65];
    __shared__ float ows[32 * 33];
    __shared__ float hbs[64];

    const int tid = threadIdx.x;
    for (int idx = tid; idx < 1024; idx += 256) {
        As[(idx >> 5) * 33 + (idx & 31)]  = Ain[idx];
        ows[(idx >> 5) * 33 + (idx & 31)] = owin[idx];
    }
    for (int idx = tid; idx < 2048; idx += 256)
        Ws[(idx >> 6) * 65 + (idx & 63)] = Win[idx];
    if (tid < 64) hbs[tid] = hbin[tid];
    __syncthreads();

    const int lane = tid & 31;
    const int b    = blockIdx.x * 8 + (tid >> 5);

    float h = 0.f, sum = 0.f;
    const float* xrow = g_xt + b * T2 * LAT + lane;

    for (int t = 0; t < T2; t++) {
        float xv = xrow[t * LAT];
        float lin = 0.f;
        float p0 = hbs[lane];
        float p1 = hbs[32 + lane];
#pragma unroll
        for (int m = 0; m < 32; m++) {
            float hm = __shfl_sync(0xffffffffu, h, m);
            lin = fmaf(As[lane * 33 + m],      hm, lin);
            p0  = fmaf(Ws[m * 65 + lane],      hm, p0);
            p1  = fmaf(Ws[m * 65 + 32 + lane], hm, p1);
        }
        float r0 = fmaxf(p0, 0.f);
        float r1 = fmaxf(p1, 0.f);
        float nl = 0.f;
#pragma unroll
        for (int j = 0; j < 32; j++)
            nl = fmaf(__shfl_sync(0xffffffffu, r0, j), Ws[lane * 65 + j], nl);
#pragma unroll
        for (int j = 0; j < 32; j++)
            nl = fmaf(__shfl_sync(0xffffffffu, r1, j), Ws[lane * 65 + 32 + j], nl);

        h = lin + nl + xv;
        sum += h;
    }

    float pooled = sum * (1.f / (float)T2);
    float o = obin[lane];
#pragma unroll
    for (int m = 0; m < 32; m++)
        o = fmaf(ows[lane * 33 + m], __shfl_sync(0xffffffffu, pooled, m), o);
    out[b * 32 + lane] = o;
}

// ---------------- launcher ----------------
extern "C" void kernel_launch(void* const* d_in, const int* in_sizes, int n_in,
                              void* d_out, int out_size) {
    const float* x       = (const float*)d_in[0];
    const float* conv1_w = (const float*)d_in[1];
    const float* bn1_g   = (const float*)d_in[3];
    const float* bn1_b   = (const float*)d_in[4];
    const float* conv2_w = (const float*)d_in[5];
    const float* bn2_g   = (const float*)d_in[7];
    const float* bn2_b   = (const float*)d_in[8];
    const float* proj_w  = (const float*)d_in[9];
    const float* proj_b  = (const float*)d_in[10];
    const float* ln_g    = (const float*)d_in[11];
    const float* ln_b    = (const float*)d_in[12];
    const float* A       = (const float*)d_in[13];
    const float* W       = (const float*)d_in[14];
    const float* h_bias  = (const float*)d_in[15];
    const float* out_w   = (const float*)d_in[16];
    const float* out_b   = (const float*)d_in[17];
    float* out = (float*)d_out;

    init_kernel<<<1, 64>>>();
    conv1_kernel<<<dim3(4, B), 128>>>(x, conv1_w);
    finalize_kernel<<<1, 32>>>(0, bn1_g, bn1_b);
    conv2_kernel<<<dim3(2, B), 128>>>(conv2_w);
    finalize_kernel<<<1, 32>>>(1, bn2_g, bn2_b);
    projln_kernel<<<512, 256>>>(proj_w, proj_b, ln_g, ln_b);
    recur_kernel<<<64, 256>>>(A, W, h_bias, out_w, out_b, out);
}

// round 6
// speedup vs baseline: 1.5326x; 1.3656x over previous
#include <cuda_runtime.h>
#include <cuda_bf16.h>

// ---------------- problem constants ----------------
#define B     512
#define C_IN  12
#define T_IN  5000
#define T1    496      // (5000-50)/10+1
#define T2    95       // (496-25)/5+1
#define NF    32
#define LAT   32
#define HID   64
#define EPSV  1e-5f

// ---------------- scratch (static device memory; no allocation) ----------------
__device__ float g_y1[B * 32 * T1];        // conv1 raw output [b][oc][t]
__device__ float g_y2t[B * T2 * NF];       // conv2 raw output TRANSPOSED [b][t][f]
__device__ float g_xt[B * T2 * LAT];       // post proj+LN [b][t][l]
__device__ float g_stats1[64];             // sum[32], sumsq[32]
__device__ float g_stats2[64];
__device__ float g_s1[32], g_sh1[32];      // BN1 scale/shift
__device__ float g_s2[32], g_sh2[32];      // BN2 scale/shift

// ---------------- init: zero stats ----------------
__global__ void init_kernel() {
    int i = threadIdx.x;
    if (i < 64) { g_stats1[i] = 0.f; g_stats2[i] = 0.f; }
}

// ---------------- conv1 + BN1 stats ----------------
// grid (8, 512): x = t-tile (64 t's), y = batch. 128 threads.
// thread tile: 4 oc x 4 t.  og = tid>>4 -> oc0 = og*4 ; tg = tid&15 -> t = t0+tg+16*i
__global__ void conv1_kernel(const float* __restrict__ x,
                             const float* __restrict__ w1,
                             const float* __restrict__ b1) {
    __shared__ __align__(16) float xs[680];     // 63*10+50 samples
    __shared__ __align__(16) float ws[1600];    // 32 oc x 50 k
    __shared__ float s_sum[32], s_sq[32];

    const int b    = blockIdx.y;
    const int t0   = blockIdx.x * 64;
    const int tid  = threadIdx.x;
    const int og   = tid >> 4;
    const int tg   = tid & 15;
    const int oc0  = og * 4;

    if (tid < 32) { s_sum[tid] = 0.f; s_sq[tid] = 0.f; }

    float acc[4][4];
#pragma unroll
    for (int j = 0; j < 4; j++)
#pragma unroll
        for (int i = 0; i < 4; i++) acc[j][i] = 0.f;

    for (int c = 0; c < C_IN; c++) {
        __syncthreads();
        const float* xrow = x + (b * C_IN + c) * T_IN + t0 * 10;
        const int lim = T_IN - t0 * 10;
        for (int s = tid; s < 680; s += 128)
            xs[s] = (s < lim) ? xrow[s] : 0.f;
        for (int idx = tid; idx < 1600; idx += 128) {
            int o = idx / 50, k = idx - o * 50;
            ws[idx] = w1[o * (C_IN * 50) + c * 50 + k];
        }
        __syncthreads();

#pragma unroll
        for (int k = 0; k < 50; k += 2) {
            float2 wv[4], xv[4];
#pragma unroll
            for (int j = 0; j < 4; j++)
                wv[j] = *(const float2*)&ws[(oc0 + j) * 50 + k];
#pragma unroll
            for (int i = 0; i < 4; i++)
                xv[i] = *(const float2*)&xs[(tg + 16 * i) * 10 + k];
#pragma unroll
            for (int j = 0; j < 4; j++)
#pragma unroll
                for (int i = 0; i < 4; i++) {
                    acc[j][i] = fmaf(wv[j].x, xv[i].x, acc[j][i]);
                    acc[j][i] = fmaf(wv[j].y, xv[i].y, acc[j][i]);
                }
        }
    }
    __syncthreads();

    float bias[4];
#pragma unroll
    for (int j = 0; j < 4; j++) bias[j] = b1[oc0 + j];

    float psum[4] = {0.f, 0.f, 0.f, 0.f};
    float psq[4]  = {0.f, 0.f, 0.f, 0.f};
#pragma unroll
    for (int i = 0; i < 4; i++) {
        int t = t0 + tg + 16 * i;
        if (t < T1) {
#pragma unroll
            for (int j = 0; j < 4; j++) {
                float v = acc[j][i] + bias[j];
                g_y1[(b * 32 + oc0 + j) * T1 + t] = v;
                psum[j] += v;
                psq[j]  += v * v;
            }
        }
    }
#pragma unroll
    for (int j = 0; j < 4; j++) {
        atomicAdd(&s_sum[oc0 + j], psum[j]);
        atomicAdd(&s_sq[oc0 + j],  psq[j]);
    }
    __syncthreads();
    if (tid < 32) {
        atomicAdd(&g_stats1[tid],      s_sum[tid]);
        atomicAdd(&g_stats1[32 + tid], s_sq[tid]);
    }
}

// ---------------- BN finalize (which: 0 -> BN1, 1 -> BN2) ----------------
__global__ void finalize_kernel(int which,
                                const float* __restrict__ g,
                                const float* __restrict__ bb) {
    int c = threadIdx.x;
    if (c >= 32) return;
    const float* st = which ? g_stats2 : g_stats1;
    float nInv = which ? (1.f / (float)(B * T2)) : (1.f / (float)(B * T1));
    float mean = st[c] * nInv;
    float var  = st[32 + c] * nInv - mean * mean;
    float s    = g[c] * rsqrtf(var + EPSV);
    if (which) { g_s2[c] = s; g_sh2[c] = bb[c] - mean * s; }
    else       { g_s1[c] = s; g_sh1[c] = bb[c] - mean * s; }
}

// ---------------- conv2 (BN1+relu on the fly) + BN2 stats ----------------
// grid (2, 512): x = t-half (48 outputs), y = batch. 128 threads.
// thread tile: 4 oc x 3 t (tl = tg + 16*i, i<3; t = tbase + tl, guard t<95)
__global__ void conv2_kernel(const float* __restrict__ w2,
                             const float* __restrict__ b2) {
    __shared__ __align__(16) float zs[260];   // relu(bn1(y1)) segment for this half
    __shared__ __align__(16) float ws[800];   // 32 oc x 25 k
    __shared__ float s_sum[32], s_sq[32];

    const int b     = blockIdx.y;
    const int tbase = blockIdx.x * 48;
    const int tid   = threadIdx.x;
    const int og    = tid >> 4;
    const int tg    = tid & 15;
    const int oc0   = og * 4;

    if (tid < 32) { s_sum[tid] = 0.f; s_sq[tid] = 0.f; }

    float acc[4][3];
#pragma unroll
    for (int j = 0; j < 4; j++)
#pragma unroll
        for (int i = 0; i < 3; i++) acc[j][i] = 0.f;

    for (int c = 0; c < 32; c++) {
        __syncthreads();
        float sc = g_s1[c], sh = g_sh1[c];
        const float* yrow = g_y1 + (b * 32 + c) * T1;
        const int g0 = tbase * 5;
        for (int s = tid; s < 260; s += 128) {
            int gi = g0 + s;
            float v = (gi < T1) ? fmaf(yrow[gi], sc, sh) : 0.f;
            zs[s] = v > 0.f ? v : 0.f;
        }
        for (int idx = tid; idx < 800; idx += 128) {
            int o = idx / 25, k = idx - o * 25;
            ws[idx] = w2[o * (32 * 25) + c * 25 + k];
        }
        __syncthreads();

#pragma unroll
        for (int k = 0; k < 25; k++) {
            float wv[4], xv[3];
#pragma unroll
            for (int j = 0; j < 4; j++) wv[j] = ws[(oc0 + j) * 25 + k];
#pragma unroll
            for (int i = 0; i < 3; i++) xv[i] = zs[(tg + 16 * i) * 5 + k];
#pragma unroll
            for (int j = 0; j < 4; j++)
#pragma unroll
                for (int i = 0; i < 3; i++)
                    acc[j][i] = fmaf(wv[j], xv[i], acc[j][i]);
        }
    }
    __syncthreads();

    float bias[4];
#pragma unroll
    for (int j = 0; j < 4; j++) bias[j] = b2[oc0 + j];

    float psum[4] = {0.f, 0.f, 0.f, 0.f};
    float psq[4]  = {0.f, 0.f, 0.f, 0.f};
#pragma unroll
    for (int i = 0; i < 3; i++) {
        int t = tbase + tg + 16 * i;
        if (t < T2) {
#pragma unroll
            for (int j = 0; j < 4; j++) {
                float v = acc[j][i] + bias[j];
                g_y2t[(b * T2 + t) * NF + oc0 + j] = v;   // transposed store
                psum[j] += v;
                psq[j]  += v * v;
            }
        }
    }
#pragma unroll
    for (int j = 0; j < 4; j++) {
        atomicAdd(&s_sum[oc0 + j], psum[j]);
        atomicAdd(&s_sq[oc0 + j],  psq[j]);
    }
    __syncthreads();
    if (tid < 32) {
        atomicAdd(&g_stats2[tid],      s_sum[tid]);
        atomicAdd(&g_stats2[32 + tid], s_sq[tid]);
    }
}

// ---------------- projection + layernorm ----------------
// warp per (b,t) token
__global__ void projln_kernel(const float* __restrict__ pw,
                              const float* __restrict__ pb,
                              const float* __restrict__ lng,
                              const float* __restrict__ lnb) {
    __shared__ float pws[32 * 33];   // pws[f*33 + l] = pw[l*32 + f]
    const int tid = threadIdx.x;
    for (int idx = tid; idx < 1024; idx += blockDim.x)
        pws[(idx & 31) * 33 + (idx >> 5)] = pw[idx];
    __syncthreads();

    const int lane   = tid & 31;
    const int warpId = (blockIdx.x * blockDim.x + tid) >> 5;
    const int nw     = (gridDim.x * blockDim.x) >> 5;

    const float s2  = g_s2[lane], sh2 = g_sh2[lane];
    const float pbv = pb[lane];
    const float lg  = lng[lane], lb = lnb[lane];

    for (int task = warpId; task < B * T2; task += nw) {
        float v = g_y2t[task * NF + lane];
        v = fmaf(v, s2, sh2);
        v = v > 0.f ? v : 0.f;

        float a = pbv;
#pragma unroll
        for (int f = 0; f < 32; f++)
            a = fmaf(__shfl_sync(0xffffffffu, v, f), pws[f * 33 + lane], a);

        float s = a;
#pragma unroll
        for (int off = 16; off > 0; off >>= 1) s += __shfl_xor_sync(0xffffffffu, s, off);
        float mean = s * (1.f / 32.f);
        float d = a - mean;
        float q = d * d;
#pragma unroll
        for (int off = 16; off > 0; off >>= 1) q += __shfl_xor_sync(0xffffffffu, q, off);
        float var = q * (1.f / 32.f);
        g_xt[task * LAT + lane] = fmaf(d * rsqrtf(var + EPSV), lg, lb);
    }
}

// ---------------- PLRNN scan + pool + output projection ----------------
// warp per batch row. grid 128 x 128 threads = 512 warps (covers more SMs).
__global__ void recur_kernel(const float* __restrict__ Ain,
                             const float* __restrict__ Win,
                             const float* __restrict__ hbin,
                             const float* __restrict__ owin,
                             const float* __restrict__ obin,
                             float* __restrict__ out) {
    __shared__ float As[32 * 33];
    __shared__ float Ws[32 * 65];
    __shared__ float ows[32 * 33];
    __shared__ float hbs[64];

    const int tid = threadIdx.x;
    for (int idx = tid; idx < 1024; idx += 128) {
        As[(idx >> 5) * 33 + (idx & 31)]  = Ain[idx];
        ows[(idx >> 5) * 33 + (idx & 31)] = owin[idx];
    }
    for (int idx = tid; idx < 2048; idx += 128)
        Ws[(idx >> 6) * 65 + (idx & 63)] = Win[idx];
    if (tid < 64) hbs[tid] = hbin[tid];
    __syncthreads();

    const int lane = tid & 31;
    const int b    = blockIdx.x * 4 + (tid >> 5);

    float h = 0.f, sum = 0.f;
    const float* xrow = g_xt + b * T2 * LAT + lane;

    for (int t = 0; t < T2; t++) {
        float xv = xrow[t * LAT];
        float lin = 0.f;
        float p0 = hbs[lane];
        float p1 = hbs[32 + lane];
#pragma unroll
        for (int m = 0; m < 32; m++) {
            float hm = __shfl_sync(0xffffffffu, h, m);
            lin = fmaf(As[lane * 33 + m],      hm, lin);
            p0  = fmaf(Ws[m * 65 + lane],      hm, p0);
            p1  = fmaf(Ws[m * 65 + 32 + lane], hm, p1);
        }
        float r0 = fmaxf(p0, 0.f);
        float r1 = fmaxf(p1, 0.f);
        float nl = 0.f;
#pragma unroll
        for (int j = 0; j < 32; j++)
            nl = fmaf(__shfl_sync(0xffffffffu, r0, j), Ws[lane * 65 + j], nl);
#pragma unroll
        for (int j = 0; j < 32; j++)
            nl = fmaf(__shfl_sync(0xffffffffu, r1, j), Ws[lane * 65 + 32 + j], nl);

        h = lin + nl + xv;
        sum += h;
    }

    float pooled = sum * (1.f / (float)T2);
    float o = obin[lane];
#pragma unroll
    for (int m = 0; m < 32; m++)
        o = fmaf(ows[lane * 33 + m], __shfl_sync(0xffffffffu, pooled, m), o);
    out[b * 32 + lane] = o;
}

// ---------------- launcher ----------------
extern "C" void kernel_launch(void* const* d_in, const int* in_sizes, int n_in,
                              void* d_out, int out_size) {
    const float* x       = (const float*)d_in[0];
    const float* conv1_w = (const float*)d_in[1];
    const float* conv1_b = (const float*)d_in[2];
    const float* bn1_g   = (const float*)d_in[3];
    const float* bn1_b   = (const float*)d_in[4];
    const float* conv2_w = (const float*)d_in[5];
    const float* conv2_b = (const float*)d_in[6];
    const float* bn2_g   = (const float*)d_in[7];
    const float* bn2_b   = (const float*)d_in[8];
    const float* proj_w  = (const float*)d_in[9];
    const float* proj_b  = (const float*)d_in[10];
    const float* ln_g    = (const float*)d_in[11];
    const float* ln_b    = (const float*)d_in[12];
    const float* A       = (const float*)d_in[13];
    const float* W       = (const float*)d_in[14];
    const float* h_bias  = (const float*)d_in[15];
    const float* out_w   = (const float*)d_in[16];
    const float* out_b   = (const float*)d_in[17];
    float* out = (float*)d_out;

    init_kernel<<<1, 64>>>();
    conv1_kernel<<<dim3(8, B), 128>>>(x, conv1_w, conv1_b);
    finalize_kernel<<<1, 32>>>(0, bn1_g, bn1_b);
    conv2_kernel<<<dim3(2, B), 128>>>(conv2_w, conv2_b);
    finalize_kernel<<<1, 32>>>(1, bn2_g, bn2_b);
    projln_kernel<<<512, 256>>>(proj_w, proj_b, ln_g, ln_b);
    recur_kernel<<<128, 128>>>(A, W, h_bias, out_w, out_b, out);
}

// round 8
// speedup vs baseline: 1.8201x; 1.1875x over previous
#include <cuda_runtime.h>
#include <cuda_bf16.h>
#include <cstdint>

// ---------------- problem constants ----------------
#define B     512
#define C_IN  12
#define T_IN  5000
#define T1    496      // (5000-50)/10+1
#define T2    95       // (496-25)/5+1
#define NF    32
#define LAT   32
#define HID   64
#define EPSV  1e-5f

// ---------------- scratch (static device memory; no allocation) ----------------
__device__ float g_y1[B * 32 * T1];        // conv1 raw output [b][oc][t] (biasless; cancels in BN)
__device__ float g_y2t[B * T2 * NF];       // conv2 raw output TRANSPOSED [b][t][f]
__device__ float g_xt[B * T2 * LAT];       // post proj+LN [b][t][l]
__device__ float g_stats1[64];             // sum[32], sumsq[32]
__device__ float g_stats2[64];
__device__ float g_s1[32], g_sh1[32];      // BN1 scale/shift
__device__ float g_s2[32], g_sh2[32];      // BN2 scale/shift

// mma.sync m16n8k16 / m16n8k8, bf16 in, fp32 accum (sm_80+ PTX; HMMA on Blackwell)
#define MMA16(c, a, b) asm volatile( \
    "mma.sync.aligned.m16n8k16.row.col.f32.bf16.bf16.f32 " \
    "{%0,%1,%2,%3}, {%4,%5,%6,%7}, {%8,%9}, {%0,%1,%2,%3};" \
    : "+f"((c)[0]), "+f"((c)[1]), "+f"((c)[2]), "+f"((c)[3]) \
    : "r"((a)[0]), "r"((a)[1]), "r"((a)[2]), "r"((a)[3]), "r"((b)[0]), "r"((b)[1]))

#define MMA8(c, a, b0) asm volatile( \
    "mma.sync.aligned.m16n8k8.row.col.f32.bf16.bf16.f32 " \
    "{%0,%1,%2,%3}, {%4,%5}, {%6}, {%0,%1,%2,%3};" \
    : "+f"((c)[0]), "+f"((c)[1]), "+f"((c)[2]), "+f"((c)[3]) \
    : "r"((a)[0]), "r"((a)[1]), "r"((b0)))

// ---------------- init: zero stats ----------------
__global__ void init_kernel() {
    int i = threadIdx.x;
    if (i < 64) { g_stats1[i] = 0.f; g_stats2[i] = 0.f; }
}

// ---------------- conv1 via mma.sync bf16 hi/lo split + BN1 stats ----------------
// grid (4, 512): x = t-tile of 128 outputs, y = batch. 128 threads (4 warps).
// GEMM per block: D[128 t][32 oc] = sum_c  A_c[128 t][56 k] * W_c[32 oc][56 k]^T
// A fragments load DIRECTLY from xh/xl (A[m][k] = xh[m*10+k]; pairs 4B-aligned).
// K pad 50->56: weight cols 50..55 zeroed, so stray x values contribute 0.
__global__ void __launch_bounds__(128) conv1_mma_kernel(const float* __restrict__ x,
                                                        const float* __restrict__ w1) {
    __shared__ __align__(16) __nv_bfloat16 xh[1336], xl[1336];   // hi/lo of x window
    __shared__ __align__(16) __nv_bfloat16 bh[32 * 56], bl[32 * 56]; // weights [oc][56]
    __shared__ float s_sum[32], s_sq[32];

    const int tid  = threadIdx.x;
    const int w    = tid >> 5;
    const int lane = tid & 31;
    const int g    = lane >> 2;     // fragment row group
    const int q    = lane & 3;      // fragment col group
    const int b    = blockIdx.y;
    const int t0   = blockIdx.x * 128;

    if (tid < 32) { s_sum[tid] = 0.f; s_sq[tid] = 0.f; }

    float acc[2][4][4] = {};   // [m-tile][n-tile][frag]

    const uint32_t* XH = (const uint32_t*)xh;
    const uint32_t* XL = (const uint32_t*)xl;
    const uint32_t* BH = (const uint32_t*)bh;
    const uint32_t* BL = (const uint32_t*)bl;

    for (int c = 0; c < C_IN; c++) {
        __syncthreads();
        // stage x window -> bf16 hi/lo (coalesced; zero beyond T_IN)
        {
            const float* xrow = x + (b * C_IN + c) * T_IN + t0 * 10;
            const int lim = T_IN - t0 * 10;
            for (int s = tid; s < 1336; s += 128) {
                float v = (s < 1320 && s < lim) ? xrow[s] : 0.f;
                __nv_bfloat16 h = __float2bfloat16(v);
                xh[s] = h;
                xl[s] = __float2bfloat16(v - __bfloat162float(h));
            }
        }
        // stage weights [32 oc][56 k] hi/lo, k>=50 zero
        for (int idx = tid; idx < 1792; idx += 128) {
            int oc = idx / 56, k = idx - oc * 56;
            float v = (k < 50) ? w1[oc * 600 + c * 50 + k] : 0.f;
            __nv_bfloat16 h = __float2bfloat16(v);
            bh[idx] = h;
            bl[idx] = __float2bfloat16(v - __bfloat162float(h));
        }
        __syncthreads();

        const int m0 = w * 32 + g;
        // three k16 steps (cols 0..47)
#pragma unroll
        for (int ks = 0; ks < 3; ks++) {
            const int ao = q + ks * 8;
            uint32_t ah[2][4], al[2][4];
#pragma unroll
            for (int mt = 0; mt < 2; mt++) {
                int i0 = 5 * (m0 + mt * 16) + ao;
                ah[mt][0] = XH[i0];      ah[mt][1] = XH[i0 + 40];
                ah[mt][2] = XH[i0 + 4];  ah[mt][3] = XH[i0 + 44];
                al[mt][0] = XL[i0];      al[mt][1] = XL[i0 + 40];
                al[mt][2] = XL[i0 + 4];  al[mt][3] = XL[i0 + 44];
            }
#pragma unroll
            for (int nt = 0; nt < 4; nt++) {
                int bi = 28 * (nt * 8 + g) + q + ks * 8;
                uint32_t bhf[2] = { BH[bi], BH[bi + 4] };
                uint32_t blf[2] = { BL[bi], BL[bi + 4] };
#pragma unroll
                for (int mt = 0; mt < 2; mt++) {
                    MMA16(acc[mt][nt], ah[mt], bhf);
                    MMA16(acc[mt][nt], ah[mt], blf);
                    MMA16(acc[mt][nt], al[mt], bhf);
                }
            }
        }
        // one k8 step (cols 48..55; 50..55 are zero weights)
        {
            const int ao = 24 + q;
            uint32_t ah[2][2], al[2][2];
#pragma unroll
            for (int mt = 0; mt < 2; mt++) {
                int i0 = 5 * (m0 + mt * 16) + ao;
                ah[mt][0] = XH[i0]; ah[mt][1] = XH[i0 + 40];
                al[mt][0] = XL[i0]; al[mt][1] = XL[i0 + 40];
            }
#pragma unroll
            for (int nt = 0; nt < 4; nt++) {
                int bi = 28 * (nt * 8 + g) + 24 + q;
                uint32_t b0h = BH[bi], b0l = BL[bi];
#pragma unroll
                for (int mt = 0; mt < 2; mt++) {
                    MMA8(acc[mt][nt], ah[mt], b0h);
                    MMA8(acc[mt][nt], ah[mt], b0l);
                    MMA8(acc[mt][nt], al[mt], b0h);
                }
            }
        }
    }

    // epilogue: C[g(+8)][2q(+1)] per tile -> g_y1 + stats
    float psum[4][2] = {}, psq[4][2] = {};
#pragma unroll
    for (int mt = 0; mt < 2; mt++) {
#pragma unroll
        for (int rr = 0; rr < 2; rr++) {
            int t = t0 + w * 32 + mt * 16 + g + rr * 8;
            if (t < T1) {
#pragma unroll
                for (int nt = 0; nt < 4; nt++) {
#pragma unroll
                    for (int j = 0; j < 2; j++) {
                        float v = acc[mt][nt][rr * 2 + j];
                        int oc = nt * 8 + q * 2 + j;
                        g_y1[(b * 32 + oc) * T1 + t] = v;
                        psum[nt][j] += v;
                        psq[nt][j]  += v * v;
                    }
                }
            }
        }
    }
#pragma unroll
    for (int nt = 0; nt < 4; nt++)
#pragma unroll
        for (int j = 0; j < 2; j++) {
            atomicAdd(&s_sum[nt * 8 + q * 2 + j], psum[nt][j]);
            atomicAdd(&s_sq [nt * 8 + q * 2 + j], psq[nt][j]);
        }
    __syncthreads();
    if (tid < 32) {
        atomicAdd(&g_stats1[tid],      s_sum[tid]);
        atomicAdd(&g_stats1[32 + tid], s_sq[tid]);
    }
}

// ---------------- BN finalize (which: 0 -> BN1, 1 -> BN2) ----------------
__global__ void finalize_kernel(int which,
                                const float* __restrict__ g,
                                const float* __restrict__ bb) {
    int c = threadIdx.x;
    if (c >= 32) return;
    const float* st = which ? g_stats2 : g_stats1;
    float nInv = which ? (1.f / (float)(B * T2)) : (1.f / (float)(B * T1));
    float mean = st[c] * nInv;
    float var  = st[32 + c] * nInv - mean * mean;
    float s    = g[c] * rsqrtf(var + EPSV);
    if (which) { g_s2[c] = s; g_sh2[c] = bb[c] - mean * s; }
    else       { g_s1[c] = s; g_sh1[c] = bb[c] - mean * s; }
}

// ---------------- conv2 (BN1+relu on the fly) + BN2 stats ----------------
// grid (2, 512): x = t-half (48 outputs), y = batch. 128 threads. 4 oc x 3 t tile.
__global__ void conv2_kernel(const float* __restrict__ w2,
                             const float* __restrict__ b2) {
    __shared__ __align__(16) float zs[260];
    __shared__ __align__(16) float ws[800];
    __shared__ float s_sum[32], s_sq[32];

    const int b     = blockIdx.y;
    const int tbase = blockIdx.x * 48;
    const int tid   = threadIdx.x;
    const int og    = tid >> 4;
    const int tg    = tid & 15;
    const int oc0   = og * 4;

    if (tid < 32) { s_sum[tid] = 0.f; s_sq[tid] = 0.f; }

    float acc[4][3];
#pragma unroll
    for (int j = 0; j < 4; j++)
#pragma unroll
        for (int i = 0; i < 3; i++) acc[j][i] = 0.f;

    for (int c = 0; c < 32; c++) {
        __syncthreads();
        float sc = g_s1[c], sh = g_sh1[c];
        const float* yrow = g_y1 + (b * 32 + c) * T1;
        const int g0 = tbase * 5;
        for (int s = tid; s < 260; s += 128) {
            int gi = g0 + s;
            float v = (gi < T1) ? fmaf(yrow[gi], sc, sh) : 0.f;
            zs[s] = v > 0.f ? v : 0.f;
        }
        for (int idx = tid; idx < 800; idx += 128) {
            int o = idx / 25, k = idx - o * 25;
            ws[idx] = w2[o * (32 * 25) + c * 25 + k];
        }
        __syncthreads();

#pragma unroll
        for (int k = 0; k < 25; k++) {
            float wv[4], xv[3];
#pragma unroll
            for (int j = 0; j < 4; j++) wv[j] = ws[(oc0 + j) * 25 + k];
#pragma unroll
            for (int i = 0; i < 3; i++) xv[i] = zs[(tg + 16 * i) * 5 + k];
#pragma unroll
            for (int j = 0; j < 4; j++)
#pragma unroll
                for (int i = 0; i < 3; i++)
                    acc[j][i] = fmaf(wv[j], xv[i], acc[j][i]);
        }
    }
    __syncthreads();

    float bias[4];
#pragma unroll
    for (int j = 0; j < 4; j++) bias[j] = b2[oc0 + j];

    float psum[4] = {0.f, 0.f, 0.f, 0.f};
    float psq[4]  = {0.f, 0.f, 0.f, 0.f};
#pragma unroll
    for (int i = 0; i < 3; i++) {
        int t = tbase + tg + 16 * i;
        if (t < T2) {
#pragma unroll
            for (int j = 0; j < 4; j++) {
                float v = acc[j][i] + bias[j];
                g_y2t[(b * T2 + t) * NF + oc0 + j] = v;
                psum[j] += v;
                psq[j]  += v * v;
            }
        }
    }
#pragma unroll
    for (int j = 0; j < 4; j++) {
        atomicAdd(&s_sum[oc0 + j], psum[j]);
        atomicAdd(&s_sq[oc0 + j],  psq[j]);
    }
    __syncthreads();
    if (tid < 32) {
        atomicAdd(&g_stats2[tid],      s_sum[tid]);
        atomicAdd(&g_stats2[32 + tid], s_sq[tid]);
    }
}

// ---------------- projection + layernorm ----------------
__global__ void projln_kernel(const float* __restrict__ pw,
                              const float* __restrict__ pb,
                              const float* __restrict__ lng,
                              const float* __restrict__ lnb) {
    __shared__ float pws[32 * 33];
    const int tid = threadIdx.x;
    for (int idx = tid; idx < 1024; idx += blockDim.x)
        pws[(idx & 31) * 33 + (idx >> 5)] = pw[idx];
    __syncthreads();

    const int lane   = tid & 31;
    const int warpId = (blockIdx.x * blockDim.x + tid) >> 5;
    const int nw     = (gridDim.x * blockDim.x) >> 5;

    const float s2  = g_s2[lane], sh2 = g_sh2[lane];
    const float pbv = pb[lane];
    const float lg  = lng[lane], lb = lnb[lane];

    for (int task = warpId; task < B * T2; task += nw) {
        float v = g_y2t[task * NF + lane];
        v = fmaf(v, s2, sh2);
        v = v > 0.f ? v : 0.f;

        float a = pbv;
#pragma unroll
        for (int f = 0; f < 32; f++)
            a = fmaf(__shfl_sync(0xffffffffu, v, f), pws[f * 33 + lane], a);

        float s = a;
#pragma unroll
        for (int off = 16; off > 0; off >>= 1) s += __shfl_xor_sync(0xffffffffu, s, off);
        float mean = s * (1.f / 32.f);
        float d = a - mean;
        float q = d * d;
#pragma unroll
        for (int off = 16; off > 0; off >>= 1) q += __shfl_xor_sync(0xffffffffu, q, off);
        float var = q * (1.f / 32.f);
        g_xt[task * LAT + lane] = fmaf(d * rsqrtf(var + EPSV), lg, lb);
    }
}

// ---------------- PLRNN scan + pool + output projection ----------------
__global__ void recur_kernel(const float* __restrict__ Ain,
                             const float* __restrict__ Win,
                             const float* __restrict__ hbin,
                             const float* __restrict__ owin,
                             const float* __restrict__ obin,
                             float* __restrict__ out) {
    __shared__ float As[32 * 33];
    __shared__ float Ws[32 * 65];
    __shared__ float ows[32 * 33];
    __shared__ float hbs[64];

    const int tid = threadIdx.x;
    for (int idx = tid; idx < 1024; idx += 128) {
        As[(idx >> 5) * 33 + (idx & 31)]  = Ain[idx];
        ows[(idx >> 5) * 33 + (idx & 31)] = owin[idx];
    }
    for (int idx = tid; idx < 2048; idx += 128)
        Ws[(idx >> 6) * 65 + (idx & 63)] = Win[idx];
    if (tid < 64) hbs[tid] = hbin[tid];
    __syncthreads();

    const int lane = tid & 31;
    const int b    = blockIdx.x * 4 + (tid >> 5);

    float h = 0.f, sum = 0.f;
    const float* xrow = g_xt + b * T2 * LAT + lane;

    for (int t = 0; t < T2; t++) {
        float xv = xrow[t * LAT];
        float lin = 0.f;
        float p0 = hbs[lane];
        float p1 = hbs[32 + lane];
#pragma unroll
        for (int m = 0; m < 32; m++) {
            float hm = __shfl_sync(0xffffffffu, h, m);
            lin = fmaf(As[lane * 33 + m],      hm, lin);
            p0  = fmaf(Ws[m * 65 + lane],      hm, p0);
            p1  = fmaf(Ws[m * 65 + 32 + lane], hm, p1);
        }
        float r0 = fmaxf(p0, 0.f);
        float r1 = fmaxf(p1, 0.f);
        float nl = 0.f;
#pragma unroll
        for (int j = 0; j < 32; j++)
            nl = fmaf(__shfl_sync(0xffffffffu, r0, j), Ws[lane * 65 + j], nl);
#pragma unroll
        for (int j = 0; j < 32; j++)
            nl = fmaf(__shfl_sync(0xffffffffu, r1, j), Ws[lane * 65 + 32 + j], nl);

        h = lin + nl + xv;
        sum += h;
    }

    float pooled = sum * (1.f / (float)T2);
    float o = obin[lane];
#pragma unroll
    for (int m = 0; m < 32; m++)
        o = fmaf(ows[lane * 33 + m], __shfl_sync(0xffffffffu, pooled, m), o);
    out[b * 32 + lane] = o;
}

// ---------------- launcher ----------------
extern "C" void kernel_launch(void* const* d_in, const int* in_sizes, int n_in,
                              void* d_out, int out_size) {
    const float* x       = (const float*)d_in[0];
    const float* conv1_w = (const float*)d_in[1];
    const float* bn1_g   = (const float*)d_in[3];
    const float* bn1_b   = (const float*)d_in[4];
    const float* conv2_w = (const float*)d_in[5];
    const float* conv2_b = (const float*)d_in[6];
    const float* bn2_g   = (const float*)d_in[7];
    const float* bn2_b   = (const float*)d_in[8];
    const float* proj_w  = (const float*)d_in[9];
    const float* proj_b  = (const float*)d_in[10];
    const float* ln_g    = (const float*)d_in[11];
    const float* ln_b    = (const float*)d_in[12];
    const float* A       = (const float*)d_in[13];
    const float* W       = (const float*)d_in[14];
    const float* h_bias  = (const float*)d_in[15];
    const float* out_w   = (const float*)d_in[16];
    const float* out_b   = (const float*)d_in[17];
    float* out = (float*)d_out;

    init_kernel<<<1, 64>>>();
    conv1_mma_kernel<<<dim3(4, B), 128>>>(x, conv1_w);
    finalize_kernel<<<1, 32>>>(0, bn1_g, bn1_b);
    conv2_kernel<<<dim3(2, B), 128>>>(conv2_w, conv2_b);
    finalize_kernel<<<1, 32>>>(1, bn2_g, bn2_b);
    projln_kernel<<<512, 256>>>(proj_w, proj_b, ln_g, ln_b);
    recur_kernel<<<128, 128>>>(A, W, h_bias, out_w, out_b, out);
}

// round 9
// speedup vs baseline: 2.0354x; 1.1183x over previous
#include <cuda_runtime.h>
#include <cuda_bf16.h>
#include <cstdint>

// ---------------- problem constants ----------------
#define B     512
#define C_IN  12
#define T_IN  5000
#define T1    496      // (5000-50)/10+1
#define T2    95       // (496-25)/5+1
#define NF    32
#define LAT   32
#define HID   64
#define EPSV  1e-5f

// ---------------- scratch (static device memory; no allocation) ----------------
__device__ float g_y1[B * 32 * T1];        // conv1 raw output [b][oc][t] (biasless; cancels in BN)
__device__ float g_y2t[B * T2 * NF];       // conv2 raw output TRANSPOSED [b][t][f]
__device__ float g_xt[B * T2 * LAT];       // post proj+LN [b][t][l]
__device__ float g_stats1[64];             // sum[32], sumsq[32]
__device__ float g_stats2[64];
__device__ float g_s1[32], g_sh1[32];      // BN1 scale/shift
__device__ float g_s2[32], g_sh2[32];      // BN2 scale/shift

// conv2 GEMM operands (bf16 hi/lo)
__device__ unsigned short g_zth[B * 512 * 32];   // z transposed [b][tt][c], hi
__device__ unsigned short g_ztl[B * 512 * 32];   // lo
__device__ unsigned short g_w2h[32 * 800];       // w2 reshaped [oc][kk], kk=k*32+c, hi
__device__ unsigned short g_w2l[32 * 800];       // lo

// mma.sync m16n8k16 / m16n8k8, bf16 in, fp32 accum (sm_80+ PTX; HMMA on Blackwell)
#define MMA16(c, a, b) asm volatile( \
    "mma.sync.aligned.m16n8k16.row.col.f32.bf16.bf16.f32 " \
    "{%0,%1,%2,%3}, {%4,%5,%6,%7}, {%8,%9}, {%0,%1,%2,%3};" \
    : "+f"((c)[0]), "+f"((c)[1]), "+f"((c)[2]), "+f"((c)[3]) \
    : "r"((a)[0]), "r"((a)[1]), "r"((a)[2]), "r"((a)[3]), "r"((b)[0]), "r"((b)[1]))

#define MMA8(c, a, b0) asm volatile( \
    "mma.sync.aligned.m16n8k8.row.col.f32.bf16.bf16.f32 " \
    "{%0,%1,%2,%3}, {%4,%5}, {%6}, {%0,%1,%2,%3};" \
    : "+f"((c)[0]), "+f"((c)[1]), "+f"((c)[2]), "+f"((c)[3]) \
    : "r"((a)[0]), "r"((a)[1]), "r"((b0)))

// ---------------- init: zero stats ----------------
__global__ void init_kernel() {
    int i = threadIdx.x;
    if (i < 64) { g_stats1[i] = 0.f; g_stats2[i] = 0.f; }
}

// ---------------- w2 reshape + bf16 split: [oc][c][k] -> [oc][k*32+c] hi/lo ----------------
__global__ void w2prep_kernel(const float* __restrict__ w2) {
    int i = blockIdx.x * blockDim.x + threadIdx.x;
    if (i >= 32 * 800) return;
    int oc = i / 800, r = i - oc * 800;
    int k = r >> 5, c = r & 31;
    float v = w2[oc * 800 + c * 25 + k];
    __nv_bfloat16 h = __float2bfloat16(v);
    g_w2h[i] = __bfloat16_as_ushort(h);
    g_w2l[i] = __bfloat16_as_ushort(__float2bfloat16(v - __bfloat162float(h)));
}

// ---------------- conv1 via mma.sync bf16 hi/lo split + BN1 stats ----------------
// grid (4, 512): x = t-tile of 128 outputs, y = batch. 128 threads (4 warps).
__global__ void __launch_bounds__(128) conv1_mma_kernel(const float* __restrict__ x,
                                                        const float* __restrict__ w1) {
    __shared__ __align__(16) __nv_bfloat16 xh[1336], xl[1336];
    __shared__ __align__(16) __nv_bfloat16 bh[32 * 56], bl[32 * 56];
    __shared__ float s_sum[32], s_sq[32];

    const int tid  = threadIdx.x;
    const int w    = tid >> 5;
    const int lane = tid & 31;
    const int g    = lane >> 2;
    const int q    = lane & 3;
    const int b    = blockIdx.y;
    const int t0   = blockIdx.x * 128;

    if (tid < 32) { s_sum[tid] = 0.f; s_sq[tid] = 0.f; }

    float acc[2][4][4] = {};

    const uint32_t* XH = (const uint32_t*)xh;
    const uint32_t* XL = (const uint32_t*)xl;
    const uint32_t* BH = (const uint32_t*)bh;
    const uint32_t* BL = (const uint32_t*)bl;

    for (int c = 0; c < C_IN; c++) {
        __syncthreads();
        {
            const float* xrow = x + (b * C_IN + c) * T_IN + t0 * 10;
            const int lim = T_IN - t0 * 10;
            for (int s = tid; s < 1336; s += 128) {
                float v = (s < 1320 && s < lim) ? xrow[s] : 0.f;
                __nv_bfloat16 h = __float2bfloat16(v);
                xh[s] = h;
                xl[s] = __float2bfloat16(v - __bfloat162float(h));
            }
        }
        for (int idx = tid; idx < 1792; idx += 128) {
            int oc = idx / 56, k = idx - oc * 56;
            float v = (k < 50) ? w1[oc * 600 + c * 50 + k] : 0.f;
            __nv_bfloat16 h = __float2bfloat16(v);
            bh[idx] = h;
            bl[idx] = __float2bfloat16(v - __bfloat162float(h));
        }
        __syncthreads();

        const int m0 = w * 32 + g;
#pragma unroll
        for (int ks = 0; ks < 3; ks++) {
            const int ao = q + ks * 8;
            uint32_t ah[2][4], al[2][4];
#pragma unroll
            for (int mt = 0; mt < 2; mt++) {
                int i0 = 5 * (m0 + mt * 16) + ao;
                ah[mt][0] = XH[i0];      ah[mt][1] = XH[i0 + 40];
                ah[mt][2] = XH[i0 + 4];  ah[mt][3] = XH[i0 + 44];
                al[mt][0] = XL[i0];      al[mt][1] = XL[i0 + 40];
                al[mt][2] = XL[i0 + 4];  al[mt][3] = XL[i0 + 44];
            }
#pragma unroll
            for (int nt = 0; nt < 4; nt++) {
                int bi = 28 * (nt * 8 + g) + q + ks * 8;
                uint32_t bhf[2] = { BH[bi], BH[bi + 4] };
                uint32_t blf[2] = { BL[bi], BL[bi + 4] };
#pragma unroll
                for (int mt = 0; mt < 2; mt++) {
                    MMA16(acc[mt][nt], ah[mt], bhf);
                    MMA16(acc[mt][nt], ah[mt], blf);
                    MMA16(acc[mt][nt], al[mt], bhf);
                }
            }
        }
        {
            const int ao = 24 + q;
            uint32_t ah[2][2], al[2][2];
#pragma unroll
            for (int mt = 0; mt < 2; mt++) {
                int i0 = 5 * (m0 + mt * 16) + ao;
                ah[mt][0] = XH[i0]; ah[mt][1] = XH[i0 + 40];
                al[mt][0] = XL[i0]; al[mt][1] = XL[i0 + 40];
            }
#pragma unroll
            for (int nt = 0; nt < 4; nt++) {
                int bi = 28 * (nt * 8 + g) + 24 + q;
                uint32_t b0h = BH[bi], b0l = BL[bi];
#pragma unroll
                for (int mt = 0; mt < 2; mt++) {
                    MMA8(acc[mt][nt], ah[mt], b0h);
                    MMA8(acc[mt][nt], ah[mt], b0l);
                    MMA8(acc[mt][nt], al[mt], b0h);
                }
            }
        }
    }

    float psum[4][2] = {}, psq[4][2] = {};
#pragma unroll
    for (int mt = 0; mt < 2; mt++) {
#pragma unroll
        for (int rr = 0; rr < 2; rr++) {
            int t = t0 + w * 32 + mt * 16 + g + rr * 8;
            if (t < T1) {
#pragma unroll
                for (int nt = 0; nt < 4; nt++) {
#pragma unroll
                    for (int j = 0; j < 2; j++) {
                        float v = acc[mt][nt][rr * 2 + j];
                        int oc = nt * 8 + q * 2 + j;
                        g_y1[(b * 32 + oc) * T1 + t] = v;
                        psum[nt][j] += v;
                        psq[nt][j]  += v * v;
                    }
                }
            }
        }
    }
#pragma unroll
    for (int nt = 0; nt < 4; nt++)
#pragma unroll
        for (int j = 0; j < 2; j++) {
            atomicAdd(&s_sum[nt * 8 + q * 2 + j], psum[nt][j]);
            atomicAdd(&s_sq [nt * 8 + q * 2 + j], psq[nt][j]);
        }
    __syncthreads();
    if (tid < 32) {
        atomicAdd(&g_stats1[tid],      s_sum[tid]);
        atomicAdd(&g_stats1[32 + tid], s_sq[tid]);
    }
}

// ---------------- BN finalize (which: 0 -> BN1, 1 -> BN2) ----------------
__global__ void finalize_kernel(int which,
                                const float* __restrict__ g,
                                const float* __restrict__ bb) {
    int c = threadIdx.x;
    if (c >= 32) return;
    const float* st = which ? g_stats2 : g_stats1;
    float nInv = which ? (1.f / (float)(B * T2)) : (1.f / (float)(B * T1));
    float mean = st[c] * nInv;
    float var  = st[32 + c] * nInv - mean * mean;
    float s    = g[c] * rsqrtf(var + EPSV);
    if (which) { g_s2[c] = s; g_sh2[c] = bb[c] - mean * s; }
    else       { g_s1[c] = s; g_sh1[c] = bb[c] - mean * s; }
}

// ---------------- zt prep: z = relu(bn1(y1)) transposed to [b][tt][c], bf16 hi/lo ----------------
// grid 512 (batch), block (32,32). 16 chunks of 32 tt rows (pad tt 496..511 with zero).
__global__ void ztprep_kernel() {
    __shared__ unsigned short th[32][33], tl[32][33];
    const int b  = blockIdx.x;
    const int tx = threadIdx.x;   // tt within chunk (read) / c (write)
    const int ty = threadIdx.y;   // c (read) / tt within chunk (write)

    const float sc = g_s1[ty], sh = g_sh1[ty];   // read-phase channel = ty

    for (int ch = 0; ch < 16; ch++) {
        const int tt = ch * 32 + tx;
        float v = 0.f;
        if (tt < T1) {
            v = fmaf(g_y1[(b * 32 + ty) * T1 + tt], sc, sh);
            v = v > 0.f ? v : 0.f;
        }
        __nv_bfloat16 h = __float2bfloat16(v);
        __syncthreads();
        th[tx][ty] = __bfloat16_as_ushort(h);
        tl[tx][ty] = __bfloat16_as_ushort(__float2bfloat16(v - __bfloat162float(h)));
        __syncthreads();
        // write: row tt0+ty, col c=tx (coalesced in tx)
        int o = (b * 512 + ch * 32 + ty) * 32 + tx;
        g_zth[o] = th[ty][tx];
        g_ztl[o] = tl[ty][tx];
    }
}

// ---------------- conv2 via single K=800 GEMM (bf16 hi/lo) + BN2 stats ----------------
// grid (2, 512): x = t-half (48 rows), y = batch. 96 threads (3 warps x m16), no tile waste.
// A[t][kk] = ztflat[5t*32 + kk]; B[oc][kk] = g_w2h/l. D -> g_y2t (transposed), biasless.
__global__ void __launch_bounds__(96) conv2_mma_kernel() {
    __shared__ __align__(16) unsigned short zah[264 * 32], zal[264 * 32]; // 16896 B each
    __shared__ __align__(16) unsigned short wbh[32 * 80],  wbl[32 * 80];  // 5120 B each
    __shared__ float s_sum[32], s_sq[32];

    const int tid  = threadIdx.x;
    const int w    = tid >> 5;      // 0..2
    const int lane = tid & 31;
    const int g    = lane >> 2;
    const int q    = lane & 3;
    const int b    = blockIdx.y;
    const int tb   = blockIdx.x * 48;

    if (tid < 32) { s_sum[tid] = 0.f; s_sq[tid] = 0.f; }

    // stage za slab: zt rows [5*tb .. 5*tb+264) (max 5*48+263 = 503 < 512)
    {
        const uint4* sh4 = (const uint4*)(g_zth + (b * 512 + 5 * tb) * 32);
        const uint4* sl4 = (const uint4*)(g_ztl + (b * 512 + 5 * tb) * 32);
        uint4* dh4 = (uint4*)zah;
        uint4* dl4 = (uint4*)zal;
        for (int i = tid; i < 1056; i += 96) {   // 264 rows * 4 uint4/row
            dh4[i] = sh4[i];
            dl4[i] = sl4[i];
        }
    }

    float acc[4][4] = {};
    const uint32_t* ZAH = (const uint32_t*)zah;
    const uint32_t* ZAL = (const uint32_t*)zal;
    const uint32_t* WBH = (const uint32_t*)wbh;
    const uint32_t* WBL = (const uint32_t*)wbl;

    const int mrow  = w * 16 + g;           // <= 39; +8 row <= 47; za row <= 5*47+24=259 < 264
    const int base0 = mrow * 80 + q;        // A row stride = 160 bf16 = 80 uint32
    const int base1 = (mrow + 8) * 80 + q;

    for (int ch = 0; ch < 10; ch++) {
        __syncthreads();   // protect wb reuse
        // stage weight chunk [32 oc][80 kk] (kk0 = ch*80); 10 uint4 per oc row
        for (int i = tid; i < 320; i += 96) {
            int oc = i / 10, j = i - oc * 10;
            ((uint4*)wbh)[oc * 10 + j] = *(const uint4*)(g_w2h + oc * 800 + ch * 80 + j * 8);
            ((uint4*)wbl)[oc * 10 + j] = *(const uint4*)(g_w2l + oc * 800 + ch * 80 + j * 8);
        }
        __syncthreads();

#pragma unroll
        for (int ksl = 0; ksl < 5; ksl++) {
            const int ao = 8 * (ch * 5 + ksl);   // uint32 offset of this k16 step
            uint32_t ah[4], al[4];
            ah[0] = ZAH[base0 + ao];     ah[1] = ZAH[base1 + ao];
            ah[2] = ZAH[base0 + ao + 4]; ah[3] = ZAH[base1 + ao + 4];
            al[0] = ZAL[base0 + ao];     al[1] = ZAL[base1 + ao];
            al[2] = ZAL[base0 + ao + 4]; al[3] = ZAL[base1 + ao + 4];
#pragma unroll
            for (int nt = 0; nt < 4; nt++) {
                int bi = (nt * 8 + g) * 40 + 8 * ksl + q;
                uint32_t bhf[2] = { WBH[bi], WBH[bi + 4] };
                uint32_t blf[2] = { WBL[bi], WBL[bi + 4] };
                MMA16(acc[nt], ah, bhf);
                MMA16(acc[nt], ah, blf);
                MMA16(acc[nt], al, bhf);
            }
        }
    }

    // epilogue: rows mrow (rr=0) and mrow+8 (rr=1); t = tb + row
    float psum[4][2] = {}, psq[4][2] = {};
#pragma unroll
    for (int rr = 0; rr < 2; rr++) {
        int t = tb + mrow + rr * 8;
        if (t < T2) {
#pragma unroll
            for (int nt = 0; nt < 4; nt++) {
#pragma unroll
                for (int j = 0; j < 2; j++) {
                    float v = acc[nt][rr * 2 + j];
                    int oc = nt * 8 + q * 2 + j;
                    g_y2t[(b * T2 + t) * NF + oc] = v;
                    psum[nt][j] += v;
                    psq[nt][j]  += v * v;
                }
            }
        }
    }
#pragma unroll
    for (int nt = 0; nt < 4; nt++)
#pragma unroll
        for (int j = 0; j < 2; j++) {
            atomicAdd(&s_sum[nt * 8 + q * 2 + j], psum[nt][j]);
            atomicAdd(&s_sq [nt * 8 + q * 2 + j], psq[nt][j]);
        }
    __syncthreads();
    if (tid < 32) {
        atomicAdd(&g_stats2[tid],      s_sum[tid]);
        atomicAdd(&g_stats2[32 + tid], s_sq[tid]);
    }
}

// ---------------- projection + layernorm ----------------
__global__ void projln_kernel(const float* __restrict__ pw,
                              const float* __restrict__ pb,
                              const float* __restrict__ lng,
                              const float* __restrict__ lnb) {
    __shared__ float pws[32 * 33];
    const int tid = threadIdx.x;
    for (int idx = tid; idx < 1024; idx += blockDim.x)
        pws[(idx & 31) * 33 + (idx >> 5)] = pw[idx];
    __syncthreads();

    const int lane   = tid & 31;
    const int warpId = (blockIdx.x * blockDim.x + tid) >> 5;
    const int nw     = (gridDim.x * blockDim.x) >> 5;

    const float s2  = g_s2[lane], sh2 = g_sh2[lane];
    const float pbv = pb[lane];
    const float lg  = lng[lane], lb = lnb[lane];

    for (int task = warpId; task < B * T2; task += nw) {
        float v = g_y2t[task * NF + lane];
        v = fmaf(v, s2, sh2);
        v = v > 0.f ? v : 0.f;

        float a = pbv;
#pragma unroll
        for (int f = 0; f < 32; f++)
            a = fmaf(__shfl_sync(0xffffffffu, v, f), pws[f * 33 + lane], a);

        float s = a;
#pragma unroll
        for (int off = 16; off > 0; off >>= 1) s += __shfl_xor_sync(0xffffffffu, s, off);
        float mean = s * (1.f / 32.f);
        float d = a - mean;
        float q = d * d;
#pragma unroll
        for (int off = 16; off > 0; off >>= 1) q += __shfl_xor_sync(0xffffffffu, q, off);
        float var = q * (1.f / 32.f);
        g_xt[task * LAT + lane] = fmaf(d * rsqrtf(var + EPSV), lg, lb);
    }
}

// ---------------- PLRNN scan + pool + output projection ----------------
__global__ void recur_kernel(const float* __restrict__ Ain,
                             const float* __restrict__ Win,
                             const float* __restrict__ hbin,
                             const float* __restrict__ owin,
                             const float* __restrict__ obin,
                             float* __restrict__ out) {
    __shared__ float As[32 * 33];
    __shared__ float Ws[32 * 65];
    __shared__ float ows[32 * 33];
    __shared__ float hbs[64];

    const int tid = threadIdx.x;
    for (int idx = tid; idx < 1024; idx += 128) {
        As[(idx >> 5) * 33 + (idx & 31)]  = Ain[idx];
        ows[(idx >> 5) * 33 + (idx & 31)] = owin[idx];
    }
    for (int idx = tid; idx < 2048; idx += 128)
        Ws[(idx >> 6) * 65 + (idx & 63)] = Win[idx];
    if (tid < 64) hbs[tid] = hbin[tid];
    __syncthreads();

    const int lane = tid & 31;
    const int b    = blockIdx.x * 4 + (tid >> 5);

    float h = 0.f, sum = 0.f;
    const float* xrow = g_xt + b * T2 * LAT + lane;

    for (int t = 0; t < T2; t++) {
        float xv = xrow[t * LAT];
        float lin = 0.f;
        float p0 = hbs[lane];
        float p1 = hbs[32 + lane];
#pragma unroll
        for (int m = 0; m < 32; m++) {
            float hm = __shfl_sync(0xffffffffu, h, m);
            lin = fmaf(As[lane * 33 + m],      hm, lin);
            p0  = fmaf(Ws[m * 65 + lane],      hm, p0);
            p1  = fmaf(Ws[m * 65 + 32 + lane], hm, p1);
        }
        float r0 = fmaxf(p0, 0.f);
        float r1 = fmaxf(p1, 0.f);
        float nl = 0.f;
#pragma unroll
        for (int j = 0; j < 32; j++)
            nl = fmaf(__shfl_sync(0xffffffffu, r0, j), Ws[lane * 65 + j], nl);
#pragma unroll
        for (int j = 0; j < 32; j++)
            nl = fmaf(__shfl_sync(0xffffffffu, r1, j), Ws[lane * 65 + 32 + j], nl);

        h = lin + nl + xv;
        sum += h;
    }

    float pooled = sum * (1.f / (float)T2);
    float o = obin[lane];
#pragma unroll
    for (int m = 0; m < 32; m++)
        o = fmaf(ows[lane * 33 + m], __shfl_sync(0xffffffffu, pooled, m), o);
    out[b * 32 + lane] = o;
}

// ---------------- launcher ----------------
extern "C" void kernel_launch(void* const* d_in, const int* in_sizes, int n_in,
                              void* d_out, int out_size) {
    const float* x       = (const float*)d_in[0];
    const float* conv1_w = (const float*)d_in[1];
    const float* bn1_g   = (const float*)d_in[3];
    const float* bn1_b   = (const float*)d_in[4];
    const float* conv2_w = (const float*)d_in[5];
    const float* bn2_g   = (const float*)d_in[7];
    const float* bn2_b   = (const float*)d_in[8];
    const float* proj_w  = (const float*)d_in[9];
    const float* proj_b  = (const float*)d_in[10];
    const float* ln_g    = (const float*)d_in[11];
    const float* ln_b    = (const float*)d_in[12];
    const float* A       = (const float*)d_in[13];
    const float* W       = (const float*)d_in[14];
    const float* h_bias  = (const float*)d_in[15];
    const float* out_w   = (const float*)d_in[16];
    const float* out_b   = (const float*)d_in[17];
    float* out = (float*)d_out;

    init_kernel<<<1, 64>>>();
    w2prep_kernel<<<(32 * 800 + 255) / 256, 256>>>(conv2_w);
    conv1_mma_kernel<<<dim3(4, B), 128>>>(x, conv1_w);
    finalize_kernel<<<1, 32>>>(0, bn1_g, bn1_b);
    ztprep_kernel<<<B, dim3(32, 32)>>>();
    conv2_mma_kernel<<<dim3(2, B), 96>>>();
    finalize_kernel<<<1, 32>>>(1, bn2_g, bn2_b);
    projln_kernel<<<512, 256>>>(proj_w, proj_b, ln_g, ln_b);
    recur_kernel<<<128, 128>>>(A, W, h_bias, out_w, out_b, out);
}

// round 11
// speedup vs baseline: 2.1817x; 1.0719x over previous
#include <cuda_runtime.h>
#include <cuda_bf16.h>
#include <cstdint>

// ---------------- problem constants ----------------
#define B     512
#define C_IN  12
#define T_IN  5000
#define T1    496      // (5000-50)/10+1
#define T2    95       // (496-25)/5+1
#define NF    32
#define LAT   32
#define HID   64
#define EPSV  1e-5f
#define NX    (B * C_IN * T_IN)

// ---------------- scratch (static device memory; no allocation) ----------------
__device__ float g_y1[B * 32 * T1];        // conv1 raw output [b][oc][t] (biasless; cancels in BN)
__device__ float g_y2t[B * T2 * NF];       // conv2 raw output TRANSPOSED [b][t][f]
__device__ float g_xt[B * T2 * LAT];       // post proj+LN [b][t][l]
__device__ float g_stats1[64];             // sum[32], sumsq[32]
__device__ float g_stats2[64];

// pre-split bf16 operands
__device__ unsigned short g_xh[NX + 512], g_xl[NX + 512];   // x hi/lo (+pad, zeroed)
__device__ unsigned short g_w1h[C_IN * 32 * 56], g_w1l[C_IN * 32 * 56]; // [c][oc][56], k>=50 zero
__device__ unsigned short g_zth[B * 512 * 32], g_ztl[B * 512 * 32];     // z transposed [b][tt][c]
__device__ unsigned short g_w2h[32 * 800], g_w2l[32 * 800];             // [oc][kk], kk=k*32+c

// mma.sync m16n8k16 / m16n8k8, bf16 in, fp32 accum (sm_80+ PTX; HMMA on Blackwell)
#define MMA16(c, a, b) asm volatile( \
    "mma.sync.aligned.m16n8k16.row.col.f32.bf16.bf16.f32 " \
    "{%0,%1,%2,%3}, {%4,%5,%6,%7}, {%8,%9}, {%0,%1,%2,%3};" \
    : "+f"((c)[0]), "+f"((c)[1]), "+f"((c)[2]), "+f"((c)[3]) \
    : "r"((a)[0]), "r"((a)[1]), "r"((a)[2]), "r"((a)[3]), "r"((b)[0]), "r"((b)[1]))

#define MMA8(c, a, b0) asm volatile( \
    "mma.sync.aligned.m16n8k8.row.col.f32.bf16.bf16.f32 " \
    "{%0,%1,%2,%3}, {%4,%5}, {%6}, {%0,%1,%2,%3};" \
    : "+f"((c)[0]), "+f"((c)[1]), "+f"((c)[2]), "+f"((c)[3]) \
    : "r"((a)[0]), "r"((a)[1]), "r"((b0)))

__device__ __forceinline__ void split_bf16(float v, unsigned short& h, unsigned short& l) {
    __nv_bfloat16 hb = __float2bfloat16(v);
    h = __bfloat16_as_ushort(hb);
    l = __bfloat16_as_ushort(__float2bfloat16(v - __bfloat162float(hb)));
}

// ---------------- prep: zero stats + split w1 & w2 ----------------
__global__ void prep_kernel(const float* __restrict__ w1, const float* __restrict__ w2) {
    int gid = blockIdx.x * blockDim.x + threadIdx.x;
    if (gid < 64) { g_stats1[gid] = 0.f; g_stats2[gid] = 0.f; }
    // w1: [oc][c][50] -> [c][oc*56 + k], k>=50 zero
    for (int i = gid; i < C_IN * 32 * 56; i += gridDim.x * blockDim.x) {
        int c = i / 1792, r = i - c * 1792;
        int oc = r / 56, k = r - oc * 56;
        float v = (k < 50) ? w1[oc * 600 + c * 50 + k] : 0.f;
        split_bf16(v, g_w1h[i], g_w1l[i]);
    }
    // w2: [oc][c][25] -> [oc][k*32+c]
    for (int i = gid; i < 32 * 800; i += gridDim.x * blockDim.x) {
        int oc = i / 800, r = i - oc * 800;
        int k = r >> 5, c = r & 31;
        split_bf16(w2[oc * 800 + c * 25 + k], g_w2h[i], g_w2l[i]);
    }
}

// ---------------- xprep: split all of x into bf16 hi/lo ----------------
__global__ void xprep_kernel(const float* __restrict__ x) {
    int gid = blockIdx.x * blockDim.x + threadIdx.x;
    int i4 = gid * 4;
    if (i4 < NX) {
        float4 v = *(const float4*)(x + i4);
        unsigned short h0, l0, h1, l1, h2, l2, h3, l3;
        split_bf16(v.x, h0, l0); split_bf16(v.y, h1, l1);
        split_bf16(v.z, h2, l2); split_bf16(v.w, h3, l3);
        uint2 ph = make_uint2(((uint32_t)h1 << 16) | h0, ((uint32_t)h3 << 16) | h2);
        uint2 pl = make_uint2(((uint32_t)l1 << 16) | l0, ((uint32_t)l3 << 16) | l2);
        *(uint2*)(g_xh + i4) = ph;
        *(uint2*)(g_xl + i4) = pl;
    }
    if (gid < 512) { g_xh[NX + gid] = 0; g_xl[NX + gid] = 0; }  // zero pad
}

// ---------------- conv1 via mma.sync (pre-split bf16) + BN1 stats ----------------
// grid (4, 512): x = t-tile of 128 outputs, y = batch. 128 threads (4 warps).
__global__ void __launch_bounds__(128) conv1_mma_kernel() {
    __shared__ __align__(16) unsigned short xh[1336], xl[1336];
    __shared__ __align__(16) unsigned short bh[32 * 56], bl[32 * 56];
    __shared__ float s_sum[32], s_sq[32];

    const int tid  = threadIdx.x;
    const int w    = tid >> 5;
    const int lane = tid & 31;
    const int g    = lane >> 2;
    const int q    = lane & 3;
    const int b    = blockIdx.y;
    const int t0   = blockIdx.x * 128;

    if (tid < 32) { s_sum[tid] = 0.f; s_sq[tid] = 0.f; }

    float acc[2][4][4] = {};

    const uint32_t* XH = (const uint32_t*)xh;
    const uint32_t* XL = (const uint32_t*)xl;
    const uint32_t* BH = (const uint32_t*)bh;
    const uint32_t* BL = (const uint32_t*)bl;

    for (int c = 0; c < C_IN; c++) {
        __syncthreads();
        // stage pre-split x window + weight slab (pure uint4 copies)
        {
            const uint4* sxh = (const uint4*)(g_xh + (b * C_IN + c) * T_IN + t0 * 10);
            const uint4* sxl = (const uint4*)(g_xl + (b * C_IN + c) * T_IN + t0 * 10);
            uint4* dxh = (uint4*)xh;
            uint4* dxl = (uint4*)xl;
            for (int i = tid; i < 167; i += 128) { dxh[i] = sxh[i]; dxl[i] = sxl[i]; }
            const uint4* swh = (const uint4*)(g_w1h + c * 1792);
            const uint4* swl = (const uint4*)(g_w1l + c * 1792);
            uint4* dbh = (uint4*)bh;
            uint4* dbl = (uint4*)bl;
            for (int i = tid; i < 224; i += 128) { dbh[i] = swh[i]; dbl[i] = swl[i]; }
        }
        __syncthreads();

        const int m0 = w * 32 + g;
#pragma unroll
        for (int ks = 0; ks < 3; ks++) {
            const int ao = q + ks * 8;
            uint32_t ah[2][4], al[2][4];
#pragma unroll
            for (int mt = 0; mt < 2; mt++) {
                int i0 = 5 * (m0 + mt * 16) + ao;
                ah[mt][0] = XH[i0];      ah[mt][1] = XH[i0 + 40];
                ah[mt][2] = XH[i0 + 4];  ah[mt][3] = XH[i0 + 44];
                al[mt][0] = XL[i0];      al[mt][1] = XL[i0 + 40];
                al[mt][2] = XL[i0 + 4];  al[mt][3] = XL[i0 + 44];
            }
#pragma unroll
            for (int nt = 0; nt < 4; nt++) {
                int bi = 28 * (nt * 8 + g) + q + ks * 8;
                uint32_t bhf[2] = { BH[bi], BH[bi + 4] };
                uint32_t blf[2] = { BL[bi], BL[bi + 4] };
#pragma unroll
                for (int mt = 0; mt < 2; mt++) {
                    MMA16(acc[mt][nt], ah[mt], bhf);
                    MMA16(acc[mt][nt], ah[mt], blf);
                    MMA16(acc[mt][nt], al[mt], bhf);
                }
            }
        }
        {
            const int ao = 24 + q;
            uint32_t ah[2][2], al[2][2];
#pragma unroll
            for (int mt = 0; mt < 2; mt++) {
                int i0 = 5 * (m0 + mt * 16) + ao;
                ah[mt][0] = XH[i0]; ah[mt][1] = XH[i0 + 40];
                al[mt][0] = XL[i0]; al[mt][1] = XL[i0 + 40];
            }
#pragma unroll
            for (int nt = 0; nt < 4; nt++) {
                int bi = 28 * (nt * 8 + g) + 24 + q;
                uint32_t b0h = BH[bi], b0l = BL[bi];
#pragma unroll
                for (int mt = 0; mt < 2; mt++) {
                    MMA8(acc[mt][nt], ah[mt], b0h);
                    MMA8(acc[mt][nt], ah[mt], b0l);
                    MMA8(acc[mt][nt], al[mt], b0h);
                }
            }
        }
    }

    float psum[4][2] = {}, psq[4][2] = {};
#pragma unroll
    for (int mt = 0; mt < 2; mt++) {
#pragma unroll
        for (int rr = 0; rr < 2; rr++) {
            int t = t0 + w * 32 + mt * 16 + g + rr * 8;
            if (t < T1) {
#pragma unroll
                for (int nt = 0; nt < 4; nt++) {
#pragma unroll
                    for (int j = 0; j < 2; j++) {
                        float v = acc[mt][nt][rr * 2 + j];
                        int oc = nt * 8 + q * 2 + j;
                        g_y1[(b * 32 + oc) * T1 + t] = v;
                        psum[nt][j] += v;
                        psq[nt][j]  += v * v;
                    }
                }
            }
        }
    }
#pragma unroll
    for (int nt = 0; nt < 4; nt++)
#pragma unroll
        for (int j = 0; j < 2; j++) {
            atomicAdd(&s_sum[nt * 8 + q * 2 + j], psum[nt][j]);
            atomicAdd(&s_sq [nt * 8 + q * 2 + j], psq[nt][j]);
        }
    __syncthreads();
    if (tid < 32) {
        atomicAdd(&g_stats1[tid],      s_sum[tid]);
        atomicAdd(&g_stats1[32 + tid], s_sq[tid]);
    }
}

// ---------------- zt prep: z = relu(bn1(y1)) transposed [b][tt][c], bf16 hi/lo ----------------
// BN1 finalize folded in (computed per block from g_stats1). grid 512, block (32,32).
__global__ void ztprep_kernel(const float* __restrict__ bn1g, const float* __restrict__ bn1b) {
    __shared__ unsigned short th[32][33], tl[32][33];
    const int b  = blockIdx.x;
    const int tx = threadIdx.x;
    const int ty = threadIdx.y;

    const float nInv = 1.f / (float)(B * T1);
    const float mean = g_stats1[ty] * nInv;
    const float var  = g_stats1[32 + ty] * nInv - mean * mean;
    const float sc   = bn1g[ty] * rsqrtf(var + EPSV);
    const float sh   = bn1b[ty] - mean * sc;

    for (int ch = 0; ch < 16; ch++) {
        const int tt = ch * 32 + tx;
        float v = 0.f;
        if (tt < T1) {
            v = fmaf(g_y1[(b * 32 + ty) * T1 + tt], sc, sh);
            v = v > 0.f ? v : 0.f;
        }
        unsigned short h, l;
        split_bf16(v, h, l);
        __syncthreads();
        th[tx][ty] = h;
        tl[tx][ty] = l;
        __syncthreads();
        int o = (b * 512 + ch * 32 + ty) * 32 + tx;
        g_zth[o] = th[ty][tx];
        g_ztl[o] = tl[ty][tx];
    }
}

// ---------------- conv2 via single K=800 GEMM (bf16 hi/lo) + BN2 stats ----------------
// grid (2, 512): x = t-half (48 rows), y = batch. 96 threads (3 warps x m16).
__global__ void __launch_bounds__(96) conv2_mma_kernel() {
    __shared__ __align__(16) unsigned short zah[264 * 32], zal[264 * 32];
    __shared__ __align__(16) unsigned short wbh[32 * 80],  wbl[32 * 80];
    __shared__ float s_sum[32], s_sq[32];

    const int tid  = threadIdx.x;
    const int w    = tid >> 5;
    const int lane = tid & 31;
    const int g    = lane >> 2;
    const int q    = lane & 3;
    const int b    = blockIdx.y;
    const int tb   = blockIdx.x * 48;

    if (tid < 32) { s_sum[tid] = 0.f; s_sq[tid] = 0.f; }

    {
        const uint4* sh4 = (const uint4*)(g_zth + (b * 512 + 5 * tb) * 32);
        const uint4* sl4 = (const uint4*)(g_ztl + (b * 512 + 5 * tb) * 32);
        uint4* dh4 = (uint4*)zah;
        uint4* dl4 = (uint4*)zal;
        for (int i = tid; i < 1056; i += 96) {
            dh4[i] = sh4[i];
            dl4[i] = sl4[i];
        }
    }

    float acc[4][4] = {};
    const uint32_t* ZAH = (const uint32_t*)zah;
    const uint32_t* ZAL = (const uint32_t*)zal;
    const uint32_t* WBH = (const uint32_t*)wbh;
    const uint32_t* WBL = (const uint32_t*)wbl;

    const int mrow  = w * 16 + g;
    const int base0 = mrow * 80 + q;
    const int base1 = (mrow + 8) * 80 + q;

    for (int ch = 0; ch < 10; ch++) {
        __syncthreads();
        for (int i = tid; i < 320; i += 96) {
            int oc = i / 10, j = i - oc * 10;
            ((uint4*)wbh)[oc * 10 + j] = *(const uint4*)(g_w2h + oc * 800 + ch * 80 + j * 8);
            ((uint4*)wbl)[oc * 10 + j] = *(const uint4*)(g_w2l + oc * 800 + ch * 80 + j * 8);
        }
        __syncthreads();

#pragma unroll
        for (int ksl = 0; ksl < 5; ksl++) {
            const int ao = 8 * (ch * 5 + ksl);
            uint32_t ah[4], al[4];
            ah[0] = ZAH[base0 + ao];     ah[1] = ZAH[base1 + ao];
            ah[2] = ZAH[base0 + ao + 4]; ah[3] = ZAH[base1 + ao + 4];
            al[0] = ZAL[base0 + ao];     al[1] = ZAL[base1 + ao];
            al[2] = ZAL[base0 + ao + 4]; al[3] = ZAL[base1 + ao + 4];
#pragma unroll
            for (int nt = 0; nt < 4; nt++) {
                int bi = (nt * 8 + g) * 40 + 8 * ksl + q;
                uint32_t bhf[2] = { WBH[bi], WBH[bi + 4] };
                uint32_t blf[2] = { WBL[bi], WBL[bi + 4] };
                MMA16(acc[nt], ah, bhf);
                MMA16(acc[nt], ah, blf);
                MMA16(acc[nt], al, bhf);
            }
        }
    }

    float psum[4][2] = {}, psq[4][2] = {};
#pragma unroll
    for (int rr = 0; rr < 2; rr++) {
        int t = tb + mrow + rr * 8;
        if (t < T2) {
#pragma unroll
            for (int nt = 0; nt < 4; nt++) {
#pragma unroll
                for (int j = 0; j < 2; j++) {
                    float v = acc[nt][rr * 2 + j];
                    int oc = nt * 8 + q * 2 + j;
                    g_y2t[(b * T2 + t) * NF + oc] = v;
                    psum[nt][j] += v;
                    psq[nt][j]  += v * v;
                }
            }
        }
    }
#pragma unroll
    for (int nt = 0; nt < 4; nt++)
#pragma unroll
        for (int j = 0; j < 2; j++) {
            atomicAdd(&s_sum[nt * 8 + q * 2 + j], psum[nt][j]);
            atomicAdd(&s_sq [nt * 8 + q * 2 + j], psq[nt][j]);
        }
    __syncthreads();
    if (tid < 32) {
        atomicAdd(&g_stats2[tid],      s_sum[tid]);
        atomicAdd(&g_stats2[32 + tid], s_sq[tid]);
    }
}

// ---------------- projection + layernorm (BN2 finalize folded in) ----------------
__global__ void projln_kernel(const float* __restrict__ pw,
                              const float* __restrict__ pb,
                              const float* __restrict__ lng,
                              const float* __restrict__ lnb,
                              const float* __restrict__ bn2g,
                              const float* __restrict__ bn2b) {
    __shared__ float pws[32 * 33];
    const int tid = threadIdx.x;
    for (int idx = tid; idx < 1024; idx += blockDim.x)
        pws[(idx & 31) * 33 + (idx >> 5)] = pw[idx];
    __syncthreads();

    const int lane   = tid & 31;
    const int warpId = (blockIdx.x * blockDim.x + tid) >> 5;
    const int nw     = (gridDim.x * blockDim.x) >> 5;

    const float nInv = 1.f / (float)(B * T2);
    const float mean = g_stats2[lane] * nInv;
    const float var  = g_stats2[32 + lane] * nInv - mean * mean;
    const float s2   = bn2g[lane] * rsqrtf(var + EPSV);
    const float sh2  = bn2b[lane] - mean * s2;

    const float pbv = pb[lane];
    const float lg  = lng[lane], lb = lnb[lane];

    for (int task = warpId; task < B * T2; task += nw) {
        float v = g_y2t[task * NF + lane];
        v = fmaf(v, s2, sh2);
        v = v > 0.f ? v : 0.f;

        float a = pbv;
#pragma unroll
        for (int f = 0; f < 32; f++)
            a = fmaf(__shfl_sync(0xffffffffu, v, f), pws[f * 33 + lane], a);

        float s = a;
#pragma unroll
        for (int off = 16; off > 0; off >>= 1) s += __shfl_xor_sync(0xffffffffu, s, off);
        float mean2 = s * (1.f / 32.f);
        float d = a - mean2;
        float qq = d * d;
#pragma unroll
        for (int off = 16; off > 0; off >>= 1) qq += __shfl_xor_sync(0xffffffffu, qq, off);
        float var2 = qq * (1.f / 32.f);
        g_xt[task * LAT + lane] = fmaf(d * rsqrtf(var2 + EPSV), lg, lb);
    }
}

// ---------------- PLRNN scan + pool + output projection ----------------
__global__ void recur_kernel(const float* __restrict__ Ain,
                             const float* __restrict__ Win,
                             const float* __restrict__ hbin,
                             const float* __restrict__ owin,
                             const float* __restrict__ obin,
                             float* __restrict__ out) {
    __shared__ float As[32 * 33];
    __shared__ float Ws[32 * 65];
    __shared__ float ows[32 * 33];
    __shared__ float hbs[64];

    const int tid = threadIdx.x;
    for (int idx = tid; idx < 1024; idx += 128) {
        As[(idx >> 5) * 33 + (idx & 31)]  = Ain[idx];
        ows[(idx >> 5) * 33 + (idx & 31)] = owin[idx];
    }
    for (int idx = tid; idx < 2048; idx += 128)
        Ws[(idx >> 6) * 65 + (idx & 63)] = Win[idx];
    if (tid < 64) hbs[tid] = hbin[tid];
    __syncthreads();

    const int lane = tid & 31;
    const int b    = blockIdx.x * 4 + (tid >> 5);

    float h = 0.f, sum = 0.f;
    const float* xrow = g_xt + b * T2 * LAT + lane;

    for (int t = 0; t < T2; t++) {
        float xv = xrow[t * LAT];
        float lin = 0.f;
        float p0 = hbs[lane];
        float p1 = hbs[32 + lane];
#pragma unroll
        for (int m = 0; m < 32; m++) {
            float hm = __shfl_sync(0xffffffffu, h, m);
            lin = fmaf(As[lane * 33 + m],      hm, lin);
            p0  = fmaf(Ws[m * 65 + lane],      hm, p0);
            p1  = fmaf(Ws[m * 65 + 32 + lane], hm, p1);
        }
        float r0 = fmaxf(p0, 0.f);
        float r1 = fmaxf(p1, 0.f);
        float nl = 0.f;
#pragma unroll
        for (int j = 0; j < 32; j++)
            nl = fmaf(__shfl_sync(0xffffffffu, r0, j), Ws[lane * 65 + j], nl);
#pragma unroll
        for (int j = 0; j < 32; j++)
            nl = fmaf(__shfl_sync(0xffffffffu, r1, j), Ws[lane * 65 + 32 + j], nl);

        h = lin + nl + xv;
        sum += h;
    }

    float pooled = sum * (1.f / (float)T2);
    float o = obin[lane];
#pragma unroll
    for (int m = 0; m < 32; m++)
        o = fmaf(ows[lane * 33 + m], __shfl_sync(0xffffffffu, pooled, m), o);
    out[b * 32 + lane] = o;
}

// ---------------- launcher ----------------
extern "C" void kernel_launch(void* const* d_in, const int* in_sizes, int n_in,
                              void* d_out, int out_size) {
    const float* x       = (const float*)d_in[0];
    const float* conv1_w = (const float*)d_in[1];
    const float* bn1_g   = (const float*)d_in[3];
    const float* bn1_b   = (const float*)d_in[4];
    const float* conv2_w = (const float*)d_in[5];
    const float* bn2_g   = (const float*)d_in[7];
    const float* bn2_b   = (const float*)d_in[8];
    const float* proj_w  = (const float*)d_in[9];
    const float* proj_b  = (const float*)d_in[10];
    const float* ln_g    = (const float*)d_in[11];
    const float* ln_b    = (const float*)d_in[12];
    const float* A       = (const float*)d_in[13];
    const float* W       = (const float*)d_in[14];
    const float* h_bias  = (const float*)d_in[15];
    const float* out_w   = (const float*)d_in[16];
    const float* out_b   = (const float*)d_in[17];
    float* out = (float*)d_out;

    prep_kernel<<<64, 256>>>(conv1_w, conv2_w);
    xprep_kernel<<<(NX / 4 + 255) / 256, 256>>>(x);
    conv1_mma_kernel<<<dim3(4, B), 128>>>();
    ztprep_kernel<<<B, dim3(32, 32)>>>(bn1_g, bn1_b);
    conv2_mma_kernel<<<dim3(2, B), 96>>>();
    projln_kernel<<<512, 256>>>(proj_w, proj_b, ln_g, ln_b, bn2_g, bn2_b);
    recur_kernel<<<128, 128>>>(A, W, h_bias, out_w, out_b, out);
}

// round 13
// speedup vs baseline: 2.4155x; 1.1071x over previous
#include <cuda_runtime.h>
#include <cuda_bf16.h>
#include <cstdint>

// ---------------- problem constants ----------------
#define B     512
#define C_IN  12
#define T_IN  5000
#define T1    496      // (5000-50)/10+1
#define T2    95       // (496-25)/5+1
#define NF    32
#define LAT   32
#define HID   64
#define EPSV  1e-5f
#define NX    (B * C_IN * T_IN)

// ---------------- scratch (static device memory; no allocation) ----------------
__device__ float g_y1t[B * 512 * 32];      // conv1 raw output T-MAJOR [b][t][oc] (rows >= T1 garbage)
__device__ float g_y2t[B * T2 * NF];       // conv2 raw output TRANSPOSED [b][t][f]
__device__ float g_xt[B * T2 * LAT];       // post proj+LN [b][t][l]
__device__ float g_stats1[64];             // sum[32], sumsq[32]
__device__ float g_stats2[64];

// pre-split bf16 operands
__device__ unsigned short g_xh[NX + 512], g_xl[NX + 512];   // x hi/lo (+pad, zeroed)
__device__ unsigned short g_w1h[C_IN * 32 * 56], g_w1l[C_IN * 32 * 56]; // [c][oc][56], k>=50 zero
__device__ unsigned short g_zth[B * 512 * 32], g_ztl[B * 512 * 32];     // z transposed [b][tt][c]
__device__ unsigned short g_w2h[32 * 800], g_w2l[32 * 800];             // [oc][kk], kk=k*32+c

// mma.sync m16n8k16 / m16n8k8, bf16 in, fp32 accum (sm_80+ PTX; HMMA on Blackwell)
#define MMA16(c, a, b) asm volatile( \
    "mma.sync.aligned.m16n8k16.row.col.f32.bf16.bf16.f32 " \
    "{%0,%1,%2,%3}, {%4,%5,%6,%7}, {%8,%9}, {%0,%1,%2,%3};" \
    : "+f"((c)[0]), "+f"((c)[1]), "+f"((c)[2]), "+f"((c)[3]) \
    : "r"((a)[0]), "r"((a)[1]), "r"((a)[2]), "r"((a)[3]), "r"((b)[0]), "r"((b)[1]))

#define MMA8(c, a, b0) asm volatile( \
    "mma.sync.aligned.m16n8k8.row.col.f32.bf16.bf16.f32 " \
    "{%0,%1,%2,%3}, {%4,%5}, {%6}, {%0,%1,%2,%3};" \
    : "+f"((c)[0]), "+f"((c)[1]), "+f"((c)[2]), "+f"((c)[3]) \
    : "r"((a)[0]), "r"((a)[1]), "r"((b0)))

__device__ __forceinline__ void split_bf16(float v, unsigned short& h, unsigned short& l) {
    __nv_bfloat16 hb = __float2bfloat16(v);
    h = __bfloat16_as_ushort(hb);
    l = __bfloat16_as_ushort(__float2bfloat16(v - __bfloat162float(hb)));
}

__device__ __forceinline__ uint32_t smem_u32(const void* p) {
    uint32_t a;
    asm("{ .reg .u64 t; cvta.to.shared.u64 t, %1; cvt.u32.u64 %0, t; }" : "=r"(a) : "l"(p));
    return a;
}
__device__ __forceinline__ void cpa16(uint32_t d, const void* s) {
    asm volatile("cp.async.ca.shared.global [%0], [%1], 16;" :: "r"(d), "l"(s));
}
#define CP_COMMIT() asm volatile("cp.async.commit_group;" ::: "memory")
#define CP_WAIT0()  asm volatile("cp.async.wait_group 0;" ::: "memory")
#define CP_WAIT1()  asm volatile("cp.async.wait_group 1;" ::: "memory")

// ---------------- prep (merged): zero stats + split w1, w2, x ----------------
__global__ void prep_all_kernel(const float* __restrict__ x,
                                const float* __restrict__ w1,
                                const float* __restrict__ w2) {
    const int gid = blockIdx.x * blockDim.x + threadIdx.x;
    const int nth = gridDim.x * blockDim.x;

    if (gid < 64) { g_stats1[gid] = 0.f; g_stats2[gid] = 0.f; }
    if (gid < 512) { g_xh[NX + gid] = 0; g_xl[NX + gid] = 0; }

    // w1: [oc][c][50] -> [c][oc*56 + k], k>=50 zero
    for (int i = gid; i < C_IN * 32 * 56; i += nth) {
        int c = i / 1792, r = i - c * 1792;
        int oc = r / 56, k = r - oc * 56;
        float v = (k < 50) ? w1[oc * 600 + c * 50 + k] : 0.f;
        split_bf16(v, g_w1h[i], g_w1l[i]);
    }
    // w2: [oc][c][25] -> [oc][k*32+c]
    for (int i = gid; i < 32 * 800; i += nth) {
        int oc = i / 800, r = i - oc * 800;
        int k = r >> 5, c = r & 31;
        split_bf16(w2[oc * 800 + c * 25 + k], g_w2h[i], g_w2l[i]);
    }
    // x: 4-wide split
    for (int i = gid; i < NX / 4; i += nth) {
        int i4 = i * 4;
        float4 v = *(const float4*)(x + i4);
        unsigned short h0, l0, h1, l1, h2, l2, h3, l3;
        split_bf16(v.x, h0, l0); split_bf16(v.y, h1, l1);
        split_bf16(v.z, h2, l2); split_bf16(v.w, h3, l3);
        *(uint2*)(g_xh + i4) = make_uint2(((uint32_t)h1 << 16) | h0, ((uint32_t)h3 << 16) | h2);
        *(uint2*)(g_xl + i4) = make_uint2(((uint32_t)l1 << 16) | l0, ((uint32_t)l3 << 16) | l2);
    }
}

// ---------------- conv1 via mma.sync (pre-split bf16, cp.async double-buffer) ----------------
// grid (4, 512): x = t-tile of 128 outputs, y = batch. 128 threads (4 warps).
__shared__ struct {} _dummy_;  // (placeholder removed below)

__global__ void __launch_bounds__(128) conv1_mma_kernel() {
    __shared__ __align__(16) unsigned short xhS[2][1344], xlS[2][1344];
    __shared__ __align__(16) unsigned short bhS[2][1792], blS[2][1792];
    __shared__ float s_sum[32], s_sq[32];

    const int tid  = threadIdx.x;
    const int w    = tid >> 5;
    const int lane = tid & 31;
    const int g    = lane >> 2;
    const int q    = lane & 3;
    const int b    = blockIdx.y;
    const int t0   = blockIdx.x * 128;

    if (tid < 32) { s_sum[tid] = 0.f; s_sq[tid] = 0.f; }

    float acc[2][4][4] = {};

    // prefetch issuing lambda-ish
    auto prefetch = [&](int c, int buf) {
        const char* sxh = (const char*)(g_xh + (b * C_IN + c) * T_IN + t0 * 10);
        const char* sxl = (const char*)(g_xl + (b * C_IN + c) * T_IN + t0 * 10);
        uint32_t dxh = smem_u32(&xhS[buf][0]);
        uint32_t dxl = smem_u32(&xlS[buf][0]);
        for (int i = tid; i < 167; i += 128) {
            cpa16(dxh + i * 16, sxh + i * 16);
            cpa16(dxl + i * 16, sxl + i * 16);
        }
        const char* swh = (const char*)(g_w1h + c * 1792);
        const char* swl = (const char*)(g_w1l + c * 1792);
        uint32_t dbh = smem_u32(&bhS[buf][0]);
        uint32_t dbl = smem_u32(&blS[buf][0]);
        for (int i = tid; i < 224; i += 128) {
            cpa16(dbh + i * 16, swh + i * 16);
            cpa16(dbl + i * 16, swl + i * 16);
        }
        CP_COMMIT();
    };

    prefetch(0, 0);

    for (int c = 0; c < C_IN; c++) {
        const int buf = c & 1;
        __syncthreads();                       // prior MMA done reading buf^1
        if (c + 1 < C_IN) { prefetch(c + 1, buf ^ 1); CP_WAIT1(); }
        else              { CP_WAIT0(); }
        __syncthreads();                       // staged data visible to all

        const uint32_t* XH = (const uint32_t*)xhS[buf];
        const uint32_t* XL = (const uint32_t*)xlS[buf];
        const uint32_t* BH = (const uint32_t*)bhS[buf];
        const uint32_t* BL = (const uint32_t*)blS[buf];

        const int m0 = w * 32 + g;
#pragma unroll
        for (int ks = 0; ks < 3; ks++) {
            const int ao = q + ks * 8;
            uint32_t ah[2][4], al[2][4];
#pragma unroll
            for (int mt = 0; mt < 2; mt++) {
                int i0 = 5 * (m0 + mt * 16) + ao;
                ah[mt][0] = XH[i0];      ah[mt][1] = XH[i0 + 40];
                ah[mt][2] = XH[i0 + 4];  ah[mt][3] = XH[i0 + 44];
                al[mt][0] = XL[i0];      al[mt][1] = XL[i0 + 40];
                al[mt][2] = XL[i0 + 4];  al[mt][3] = XL[i0 + 44];
            }
#pragma unroll
            for (int nt = 0; nt < 4; nt++) {
                int bi = 28 * (nt * 8 + g) + q + ks * 8;
                uint32_t bhf[2] = { BH[bi], BH[bi + 4] };
                uint32_t blf[2] = { BL[bi], BL[bi + 4] };
#pragma unroll
                for (int mt = 0; mt < 2; mt++) {
                    MMA16(acc[mt][nt], ah[mt], bhf);
                    MMA16(acc[mt][nt], ah[mt], blf);
                    MMA16(acc[mt][nt], al[mt], bhf);
                }
            }
        }
        {
            const int ao = 24 + q;
            uint32_t ah[2][2], al[2][2];
#pragma unroll
            for (int mt = 0; mt < 2; mt++) {
                int i0 = 5 * (m0 + mt * 16) + ao;
                ah[mt][0] = XH[i0]; ah[mt][1] = XH[i0 + 40];
                al[mt][0] = XL[i0]; al[mt][1] = XL[i0 + 40];
            }
#pragma unroll
            for (int nt = 0; nt < 4; nt++) {
                int bi = 28 * (nt * 8 + g) + 24 + q;
                uint32_t b0h = BH[bi], b0l = BL[bi];
#pragma unroll
                for (int mt = 0; mt < 2; mt++) {
                    MMA8(acc[mt][nt], ah[mt], b0h);
                    MMA8(acc[mt][nt], ah[mt], b0l);
                    MMA8(acc[mt][nt], al[mt], b0h);
                }
            }
        }
    }

    // epilogue: T-MAJOR store g_y1t[(b*512 + t)*32 + oc]
    float psum[4][2] = {}, psq[4][2] = {};
#pragma unroll
    for (int mt = 0; mt < 2; mt++) {
#pragma unroll
        for (int rr = 0; rr < 2; rr++) {
            int t = t0 + w * 32 + mt * 16 + g + rr * 8;
            if (t < T1) {
                float* drow = g_y1t + (b * 512 + t) * 32;
#pragma unroll
                for (int nt = 0; nt < 4; nt++) {
#pragma unroll
                    for (int j = 0; j < 2; j++) {
                        float v = acc[mt][nt][rr * 2 + j];
                        drow[nt * 8 + q * 2 + j] = v;
                        psum[nt][j] += v;
                        psq[nt][j]  += v * v;
                    }
                }
            }
        }
    }
#pragma unroll
    for (int nt = 0; nt < 4; nt++)
#pragma unroll
        for (int j = 0; j < 2; j++) {
            atomicAdd(&s_sum[nt * 8 + q * 2 + j], psum[nt][j]);
            atomicAdd(&s_sq [nt * 8 + q * 2 + j], psq[nt][j]);
        }
    __syncthreads();
    if (tid < 32) {
        atomicAdd(&g_stats1[tid],      s_sum[tid]);
        atomicAdd(&g_stats1[32 + tid], s_sq[tid]);
    }
}

// ---------------- zt prep (streaming): z = relu(bn1(y1t)) -> bf16 hi/lo, same layout ----------------
// grid 4096 x 256: thread handles 8 consecutive channel entries (16B in / 16B+16B out).
__global__ void __launch_bounds__(256) ztprep_kernel(const float* __restrict__ bn1g,
                                                     const float* __restrict__ bn1b) {
    __shared__ float scs[32], shs[32];
    const int tid = threadIdx.x;
    if (tid < 32) {
        const float nInv = 1.f / (float)(B * T1);
        const float mean = g_stats1[tid] * nInv;
        const float var  = g_stats1[32 + tid] * nInv - mean * mean;
        const float sc   = bn1g[tid] * rsqrtf(var + EPSV);
        scs[tid] = sc;
        shs[tid] = bn1b[tid] - mean * sc;
    }
    __syncthreads();

    const int idx8 = blockIdx.x * 256 + tid;      // exactly B*512*32/8 threads
    const int base = idx8 * 8;
    const int c0   = base & 31;
    const int tt   = (base >> 5) & 511;

    unsigned short h[8], l[8];
    if (tt < T1) {
        float4 f0 = *(const float4*)(g_y1t + base);
        float4 f1 = *(const float4*)(g_y1t + base + 4);
        float vv[8] = { f0.x, f0.y, f0.z, f0.w, f1.x, f1.y, f1.z, f1.w };
#pragma unroll
        for (int i = 0; i < 8; i++) {
            float v = fmaf(vv[i], scs[c0 + i], shs[c0 + i]);
            v = v > 0.f ? v : 0.f;
            split_bf16(v, h[i], l[i]);
        }
    } else {
#pragma unroll
        for (int i = 0; i < 8; i++) { h[i] = 0; l[i] = 0; }
    }
    uint4 ph = make_uint4(((uint32_t)h[1] << 16) | h[0], ((uint32_t)h[3] << 16) | h[2],
                          ((uint32_t)h[5] << 16) | h[4], ((uint32_t)h[7] << 16) | h[6]);
    uint4 pl = make_uint4(((uint32_t)l[1] << 16) | l[0], ((uint32_t)l[3] << 16) | l[2],
                          ((uint32_t)l[5] << 16) | l[4], ((uint32_t)l[7] << 16) | l[6]);
    *(uint4*)(g_zth + base) = ph;
    *(uint4*)(g_ztl + base) = pl;
}

// ---------------- conv2 via single K=800 GEMM (bf16 hi/lo) + BN2 stats ----------------
// grid (2, 512): x = t-half (48 rows), y = batch. 96 threads (3 warps x m16).
__global__ void __launch_bounds__(96) conv2_mma_kernel() {
    __shared__ __align__(16) unsigned short zah[264 * 32], zal[264 * 32];
    __shared__ __align__(16) unsigned short wbh[32 * 80],  wbl[32 * 80];
    __shared__ float s_sum[32], s_sq[32];

    const int tid  = threadIdx.x;
    const int w    = tid >> 5;
    const int lane = tid & 31;
    const int g    = lane >> 2;
    const int q    = lane & 3;
    const int b    = blockIdx.y;
    const int tb   = blockIdx.x * 48;

    if (tid < 32) { s_sum[tid] = 0.f; s_sq[tid] = 0.f; }

    {
        const uint4* sh4 = (const uint4*)(g_zth + (b * 512 + 5 * tb) * 32);
        const uint4* sl4 = (const uint4*)(g_ztl + (b * 512 + 5 * tb) * 32);
        uint4* dh4 = (uint4*)zah;
        uint4* dl4 = (uint4*)zal;
        for (int i = tid; i < 1056; i += 96) {
            dh4[i] = sh4[i];
            dl4[i] = sl4[i];
        }
    }

    float acc[4][4] = {};
    const uint32_t* ZAH = (const uint32_t*)zah;
    const uint32_t* ZAL = (const uint32_t*)zal;
    const uint32_t* WBH = (const uint32_t*)wbh;
    const uint32_t* WBL = (const uint32_t*)wbl;

    const int mrow  = w * 16 + g;
    const int base0 = mrow * 80 + q;
    const int base1 = (mrow + 8) * 80 + q;

    for (int ch = 0; ch < 10; ch++) {
        __syncthreads();
        for (int i = tid; i < 320; i += 96) {
            int oc = i / 10, j = i - oc * 10;
            ((uint4*)wbh)[oc * 10 + j] = *(const uint4*)(g_w2h + oc * 800 + ch * 80 + j * 8);
            ((uint4*)wbl)[oc * 10 + j] = *(const uint4*)(g_w2l + oc * 800 + ch * 80 + j * 8);
        }
        __syncthreads();

#pragma unroll
        for (int ksl = 0; ksl < 5; ksl++) {
            const int ao = 8 * (ch * 5 + ksl);
            uint32_t ah[4], al[4];
            ah[0] = ZAH[base0 + ao];     ah[1] = ZAH[base1 + ao];
            ah[2] = ZAH[base0 + ao + 4]; ah[3] = ZAH[base1 + ao + 4];
            al[0] = ZAL[base0 + ao];     al[1] = ZAL[base1 + ao];
            al[2] = ZAL[base0 + ao + 4]; al[3] = ZAL[base1 + ao + 4];
#pragma unroll
            for (int nt = 0; nt < 4; nt++) {
                int bi = (nt * 8 + g) * 40 + 8 * ksl + q;
                uint32_t bhf[2] = { WBH[bi], WBH[bi + 4] };
                uint32_t blf[2] = { WBL[bi], WBL[bi + 4] };
                MMA16(acc[nt], ah, bhf);
                MMA16(acc[nt], ah, blf);
                MMA16(acc[nt], al, bhf);
            }
        }
    }

    float psum[4][2] = {}, psq[4][2] = {};
#pragma unroll
    for (int rr = 0; rr < 2; rr++) {
        int t = tb + mrow + rr * 8;
        if (t < T2) {
#pragma unroll
            for (int nt = 0; nt < 4; nt++) {
#pragma unroll
                for (int j = 0; j < 2; j++) {
                    float v = acc[nt][rr * 2 + j];
                    int oc = nt * 8 + q * 2 + j;
                    g_y2t[(b * T2 + t) * NF + oc] = v;
                    psum[nt][j] += v;
                    psq[nt][j]  += v * v;
                }
            }
        }
    }
#pragma unroll
    for (int nt = 0; nt < 4; nt++)
#pragma unroll
        for (int j = 0; j < 2; j++) {
            atomicAdd(&s_sum[nt * 8 + q * 2 + j], psum[nt][j]);
            atomicAdd(&s_sq [nt * 8 + q * 2 + j], psq[nt][j]);
        }
    __syncthreads();
    if (tid < 32) {
        atomicAdd(&g_stats2[tid],      s_sum[tid]);
        atomicAdd(&g_stats2[32 + tid], s_sq[tid]);
    }
}

// ---------------- projection + layernorm (BN2 finalize folded in) ----------------
__global__ void projln_kernel(const float* __restrict__ pw,
                              const float* __restrict__ pb,
                              const float* __restrict__ lng,
                              const float* __restrict__ lnb,
                              const float* __restrict__ bn2g,
                              const float* __restrict__ bn2b) {
    __shared__ float pws[32 * 33];
    const int tid = threadIdx.x;
    for (int idx = tid; idx < 1024; idx += blockDim.x)
        pws[(idx & 31) * 33 + (idx >> 5)] = pw[idx];
    __syncthreads();

    const int lane   = tid & 31;
    const int warpId = (blockIdx.x * blockDim.x + tid) >> 5;
    const int nw     = (gridDim.x * blockDim.x) >> 5;

    const float nInv = 1.f / (float)(B * T2);
    const float mean = g_stats2[lane] * nInv;
    const float var  = g_stats2[32 + lane] * nInv - mean * mean;
    const float s2   = bn2g[lane] * rsqrtf(var + EPSV);
    const float sh2  = bn2b[lane] - mean * s2;

    const float pbv = pb[lane];
    const float lg  = lng[lane], lb = lnb[lane];

    for (int task = warpId; task < B * T2; task += nw) {
        float v = g_y2t[task * NF + lane];
        v = fmaf(v, s2, sh2);
        v = v > 0.f ? v : 0.f;

        float a = pbv;
#pragma unroll
        for (int f = 0; f < 32; f++)
            a = fmaf(__shfl_sync(0xffffffffu, v, f), pws[f * 33 + lane], a);

        float s = a;
#pragma unroll
        for (int off = 16; off > 0; off >>= 1) s += __shfl_xor_sync(0xffffffffu, s, off);
        float mean2 = s * (1.f / 32.f);
        float d = a - mean2;
        float qq = d * d;
#pragma unroll
        for (int off = 16; off > 0; off >>= 1) qq += __shfl_xor_sync(0xffffffffu, qq, off);
        float var2 = qq * (1.f / 32.f);
        g_xt[task * LAT + lane] = fmaf(d * rsqrtf(var2 + EPSV), lg, lb);
    }
}

// ---------------- PLRNN scan + pool + output projection ----------------
__global__ void recur_kernel(const float* __restrict__ Ain,
                             const float* __restrict__ Win,
                             const float* __restrict__ hbin,
                             const float* __restrict__ owin,
                             const float* __restrict__ obin,
                             float* __restrict__ out) {
    __shared__ float As[32 * 33];
    __shared__ float Ws[32 * 65];
    __shared__ float ows[32 * 33];
    __shared__ float hbs[64];

    const int tid = threadIdx.x;
    for (int idx = tid; idx < 1024; idx += 128) {
        As[(idx >> 5) * 33 + (idx & 31)]  = Ain[idx];
        ows[(idx >> 5) * 33 + (idx & 31)] = owin[idx];
    }
    for (int idx = tid; idx < 2048; idx += 128)
        Ws[(idx >> 6) * 65 + (idx & 63)] = Win[idx];
    if (tid < 64) hbs[tid] = hbin[tid];
    __syncthreads();

    const int lane = tid & 31;
    const int b    = blockIdx.x * 4 + (tid >> 5);

    float h = 0.f, sum = 0.f;
    const float* xrow = g_xt + b * T2 * LAT + lane;

    for (int t = 0; t < T2; t++) {
        float xv = xrow[t * LAT];
        float lin = 0.f;
        float p0 = hbs[lane];
        float p1 = hbs[32 + lane];
#pragma unroll
        for (int m = 0; m < 32; m++) {
            float hm = __shfl_sync(0xffffffffu, h, m);
            lin = fmaf(As[lane * 33 + m],      hm, lin);
            p0  = fmaf(Ws[m * 65 + lane],      hm, p0);
            p1  = fmaf(Ws[m * 65 + 32 + lane], hm, p1);
        }
        float r0 = fmaxf(p0, 0.f);
        float r1 = fmaxf(p1, 0.f);
        float nl = 0.f;
#pragma unroll
        for (int j = 0; j < 32; j++)
            nl = fmaf(__shfl_sync(0xffffffffu, r0, j), Ws[lane * 65 + j], nl);
#pragma unroll
        for (int j = 0; j < 32; j++)
            nl = fmaf(__shfl_sync(0xffffffffu, r1, j), Ws[lane * 65 + 32 + j], nl);

        h = lin + nl + xv;
        sum += h;
    }

    float pooled = sum * (1.f / (float)T2);
    float o = obin[lane];
#pragma unroll
    for (int m = 0; m < 32; m++)
        o = fmaf(ows[lane * 33 + m], __shfl_sync(0xffffffffu, pooled, m), o);
    out[b * 32 + lane] = o;
}

// ---------------- launcher ----------------
extern "C" void kernel_launch(void* const* d_in, const int* in_sizes, int n_in,
                              void* d_out, int out_size) {
    const float* x       = (const float*)d_in[0];
    const float* conv1_w = (const float*)d_in[1];
    const float* bn1_g   = (const float*)d_in[3];
    const float* bn1_b   = (const float*)d_in[4];
    const float* conv2_w = (const float*)d_in[5];
    const float* bn2_g   = (const float*)d_in[7];
    const float* bn2_b   = (const float*)d_in[8];
    const float* proj_w  = (const float*)d_in[9];
    const float* proj_b  = (const float*)d_in[10];
    const float* ln_g    = (const float*)d_in[11];
    const float* ln_b    = (const float*)d_in[12];
    const float* A       = (const float*)d_in[13];
    const float* W       = (const float*)d_in[14];
    const float* h_bias  = (const float*)d_in[15];
    const float* out_w   = (const float*)d_in[16];
    const float* out_b   = (const float*)d_in[17];
    float* out = (float*)d_out;

    prep_all_kernel<<<4096, 256>>>(x, conv1_w, conv2_w);
    conv1_mma_kernel<<<dim3(4, B), 128>>>();
    ztprep_kernel<<<4096, 256>>>(bn1_g, bn1_b);
    conv2_mma_kernel<<<dim3(2, B), 96>>>();
    projln_kernel<<<512, 256>>>(proj_w, proj_b, ln_g, ln_b, bn2_g, bn2_b);
    recur_kernel<<<128, 128>>>(A, W, h_bias, out_w, out_b, out);
}

// round 15
// speedup vs baseline: 2.4333x; 1.0074x over previous
#include <cuda_runtime.h>
#include <cuda_bf16.h>
#include <cstdint>

// ---------------- problem constants ----------------
#define B     512
#define C_IN  12
#define T_IN  5000
#define T1    496      // (5000-50)/10+1
#define T2    95       // (496-25)/5+1
#define NF    32
#define LAT   32
#define HID   64
#define EPSV  1e-5f
#define NX    (B * C_IN * T_IN)

// ---------------- scratch (static device memory; no allocation) ----------------
__device__ float g_y1t[B * 512 * 32];      // conv1 raw output T-MAJOR [b][t][oc] (rows >= T1 garbage)
__device__ float g_y2t[B * T2 * NF];       // conv2 raw output TRANSPOSED [b][t][f]
__device__ float g_xt[B * T2 * LAT];       // post proj+LN [b][t][l]
__device__ float g_stats1[64];             // sum[32], sumsq[32]
__device__ float g_stats2[64];

// pre-split bf16 operands
__device__ unsigned short g_xh[NX + 512], g_xl[NX + 512];   // x hi/lo (+pad, zeroed)
__device__ unsigned short g_w1h[C_IN * 32 * 56], g_w1l[C_IN * 32 * 56]; // [c][oc][56], k>=50 zero
__device__ unsigned short g_zth[B * 512 * 32], g_ztl[B * 512 * 32];     // z transposed [b][tt][c] (tt>=496 zero)
__device__ unsigned short g_w2h[32 * 800], g_w2l[32 * 800];             // [oc][kk], kk=k*32+c

// mma.sync m16n8k16 / m16n8k8, bf16 in, fp32 accum (sm_80+ PTX; HMMA on Blackwell)
#define MMA16(c, a, b) asm volatile( \
    "mma.sync.aligned.m16n8k16.row.col.f32.bf16.bf16.f32 " \
    "{%0,%1,%2,%3}, {%4,%5,%6,%7}, {%8,%9}, {%0,%1,%2,%3};" \
    : "+f"((c)[0]), "+f"((c)[1]), "+f"((c)[2]), "+f"((c)[3]) \
    : "r"((a)[0]), "r"((a)[1]), "r"((a)[2]), "r"((a)[3]), "r"((b)[0]), "r"((b)[1]))

#define MMA8(c, a, b0) asm volatile( \
    "mma.sync.aligned.m16n8k8.row.col.f32.bf16.bf16.f32 " \
    "{%0,%1,%2,%3}, {%4,%5}, {%6}, {%0,%1,%2,%3};" \
    : "+f"((c)[0]), "+f"((c)[1]), "+f"((c)[2]), "+f"((c)[3]) \
    : "r"((a)[0]), "r"((a)[1]), "r"((b0)))

__device__ __forceinline__ void split_bf16(float v, unsigned short& h, unsigned short& l) {
    __nv_bfloat16 hb = __float2bfloat16(v);
    h = __bfloat16_as_ushort(hb);
    l = __bfloat16_as_ushort(__float2bfloat16(v - __bfloat162float(hb)));
}

__device__ __forceinline__ uint32_t smem_u32(const void* p) {
    uint32_t a;
    asm("{ .reg .u64 t; cvta.to.shared.u64 t, %1; cvt.u32.u64 %0, t; }" : "=r"(a) : "l"(p));
    return a;
}
__device__ __forceinline__ void cpa16(uint32_t d, const void* s) {
    asm volatile("cp.async.ca.shared.global [%0], [%1], 16;" :: "r"(d), "l"(s));
}
#define CP_COMMIT() asm volatile("cp.async.commit_group;" ::: "memory")
#define CP_WAIT0()  asm volatile("cp.async.wait_group 0;" ::: "memory")
#define CP_WAIT1()  asm volatile("cp.async.wait_group 1;" ::: "memory")

// ---------------- prep (merged): zero stats + split w1, w2, x ----------------
__global__ void prep_all_kernel(const float* __restrict__ x,
                                const float* __restrict__ w1,
                                const float* __restrict__ w2) {
    const int gid = blockIdx.x * blockDim.x + threadIdx.x;
    const int nth = gridDim.x * blockDim.x;

    if (gid < 64) { g_stats1[gid] = 0.f; g_stats2[gid] = 0.f; }
    if (gid < 512) { g_xh[NX + gid] = 0; g_xl[NX + gid] = 0; }

    for (int i = gid; i < C_IN * 32 * 56; i += nth) {
        int c = i / 1792, r = i - c * 1792;
        int oc = r / 56, k = r - oc * 56;
        float v = (k < 50) ? w1[oc * 600 + c * 50 + k] : 0.f;
        split_bf16(v, g_w1h[i], g_w1l[i]);
    }
    for (int i = gid; i < 32 * 800; i += nth) {
        int oc = i / 800, r = i - oc * 800;
        int k = r >> 5, c = r & 31;
        split_bf16(w2[oc * 800 + c * 25 + k], g_w2h[i], g_w2l[i]);
    }
    for (int i = gid; i < NX / 4; i += nth) {
        int i4 = i * 4;
        float4 v = *(const float4*)(x + i4);
        unsigned short h0, l0, h1, l1, h2, l2, h3, l3;
        split_bf16(v.x, h0, l0); split_bf16(v.y, h1, l1);
        split_bf16(v.z, h2, l2); split_bf16(v.w, h3, l3);
        *(uint2*)(g_xh + i4) = make_uint2(((uint32_t)h1 << 16) | h0, ((uint32_t)h3 << 16) | h2);
        *(uint2*)(g_xl + i4) = make_uint2(((uint32_t)l1 << 16) | l0, ((uint32_t)l3 << 16) | l2);
    }
}

// ---------------- conv1 via mma.sync (pre-split bf16, cp.async double-buffer) ----------------
// grid (4, 512): x = t-tile of 128 outputs, y = batch. 128 threads (4 warps).
__global__ void __launch_bounds__(128) conv1_mma_kernel() {
    __shared__ __align__(16) unsigned short xhS[2][1344], xlS[2][1344];
    __shared__ __align__(16) unsigned short bhS[2][1792], blS[2][1792];
    __shared__ float s_sum[32], s_sq[32];

    const int tid  = threadIdx.x;
    const int w    = tid >> 5;
    const int lane = tid & 31;
    const int g    = lane >> 2;
    const int q    = lane & 3;
    const int b    = blockIdx.y;
    const int t0   = blockIdx.x * 128;

    if (tid < 32) { s_sum[tid] = 0.f; s_sq[tid] = 0.f; }

    float acc[2][4][4] = {};

    auto prefetch = [&](int c, int buf) {
        const char* sxh = (const char*)(g_xh + (b * C_IN + c) * T_IN + t0 * 10);
        const char* sxl = (const char*)(g_xl + (b * C_IN + c) * T_IN + t0 * 10);
        uint32_t dxh = smem_u32(&xhS[buf][0]);
        uint32_t dxl = smem_u32(&xlS[buf][0]);
        for (int i = tid; i < 167; i += 128) {
            cpa16(dxh + i * 16, sxh + i * 16);
            cpa16(dxl + i * 16, sxl + i * 16);
        }
        const char* swh = (const char*)(g_w1h + c * 1792);
        const char* swl = (const char*)(g_w1l + c * 1792);
        uint32_t dbh = smem_u32(&bhS[buf][0]);
        uint32_t dbl = smem_u32(&blS[buf][0]);
        for (int i = tid; i < 224; i += 128) {
            cpa16(dbh + i * 16, swh + i * 16);
            cpa16(dbl + i * 16, swl + i * 16);
        }
        CP_COMMIT();
    };

    prefetch(0, 0);

    for (int c = 0; c < C_IN; c++) {
        const int buf = c & 1;
        __syncthreads();
        if (c + 1 < C_IN) { prefetch(c + 1, buf ^ 1); CP_WAIT1(); }
        else              { CP_WAIT0(); }
        __syncthreads();

        const uint32_t* XH = (const uint32_t*)xhS[buf];
        const uint32_t* XL = (const uint32_t*)xlS[buf];
        const uint32_t* BH = (const uint32_t*)bhS[buf];
        const uint32_t* BL = (const uint32_t*)blS[buf];

        const int m0 = w * 32 + g;
#pragma unroll
        for (int ks = 0; ks < 3; ks++) {
            const int ao = q + ks * 8;
            uint32_t ah[2][4], al[2][4];
#pragma unroll
            for (int mt = 0; mt < 2; mt++) {
                int i0 = 5 * (m0 + mt * 16) + ao;
                ah[mt][0] = XH[i0];      ah[mt][1] = XH[i0 + 40];
                ah[mt][2] = XH[i0 + 4];  ah[mt][3] = XH[i0 + 44];
                al[mt][0] = XL[i0];      al[mt][1] = XL[i0 + 40];
                al[mt][2] = XL[i0 + 4];  al[mt][3] = XL[i0 + 44];
            }
#pragma unroll
            for (int nt = 0; nt < 4; nt++) {
                int bi = 28 * (nt * 8 + g) + q + ks * 8;
                uint32_t bhf[2] = { BH[bi], BH[bi + 4] };
                uint32_t blf[2] = { BL[bi], BL[bi + 4] };
#pragma unroll
                for (int mt = 0; mt < 2; mt++) {
                    MMA16(acc[mt][nt], ah[mt], bhf);
                    MMA16(acc[mt][nt], ah[mt], blf);
                    MMA16(acc[mt][nt], al[mt], bhf);
                }
            }
        }
        {
            const int ao = 24 + q;
            uint32_t ah[2][2], al[2][2];
#pragma unroll
            for (int mt = 0; mt < 2; mt++) {
                int i0 = 5 * (m0 + mt * 16) + ao;
                ah[mt][0] = XH[i0]; ah[mt][1] = XH[i0 + 40];
                al[mt][0] = XL[i0]; al[mt][1] = XL[i0 + 40];
            }
#pragma unroll
            for (int nt = 0; nt < 4; nt++) {
                int bi = 28 * (nt * 8 + g) + 24 + q;
                uint32_t b0h = BH[bi], b0l = BL[bi];
#pragma unroll
                for (int mt = 0; mt < 2; mt++) {
                    MMA8(acc[mt][nt], ah[mt], b0h);
                    MMA8(acc[mt][nt], ah[mt], b0l);
                    MMA8(acc[mt][nt], al[mt], b0h);
                }
            }
        }
    }

    float psum[4][2] = {}, psq[4][2] = {};
#pragma unroll
    for (int mt = 0; mt < 2; mt++) {
#pragma unroll
        for (int rr = 0; rr < 2; rr++) {
            int t = t0 + w * 32 + mt * 16 + g + rr * 8;
            if (t < T1) {
                float* drow = g_y1t + (b * 512 + t) * 32;
#pragma unroll
                for (int nt = 0; nt < 4; nt++) {
#pragma unroll
                    for (int j = 0; j < 2; j++) {
                        float v = acc[mt][nt][rr * 2 + j];
                        drow[nt * 8 + q * 2 + j] = v;
                        psum[nt][j] += v;
                        psq[nt][j]  += v * v;
                    }
                }
            }
        }
    }
#pragma unroll
    for (int nt = 0; nt < 4; nt++)
#pragma unroll
        for (int j = 0; j < 2; j++) {
            atomicAdd(&s_sum[nt * 8 + q * 2 + j], psum[nt][j]);
            atomicAdd(&s_sq [nt * 8 + q * 2 + j], psq[nt][j]);
        }
    __syncthreads();
    if (tid < 32) {
        atomicAdd(&g_stats1[tid],      s_sum[tid]);
        atomicAdd(&g_stats1[32 + tid], s_sq[tid]);
    }
}

// ---------------- zt prep (streaming): z = relu(bn1(y1t)) -> bf16 hi/lo, same layout ----------------
__global__ void __launch_bounds__(256) ztprep_kernel(const float* __restrict__ bn1g,
                                                     const float* __restrict__ bn1b) {
    __shared__ float scs[32], shs[32];
    const int tid = threadIdx.x;
    if (tid < 32) {
        const float nInv = 1.f / (float)(B * T1);
        const float mean = g_stats1[tid] * nInv;
        const float var  = g_stats1[32 + tid] * nInv - mean * mean;
        const float sc   = bn1g[tid] * rsqrtf(var + EPSV);
        scs[tid] = sc;
        shs[tid] = bn1b[tid] - mean * sc;
    }
    __syncthreads();

    const int idx8 = blockIdx.x * 256 + tid;
    const int base = idx8 * 8;
    const int c0   = base & 31;
    const int tt   = (base >> 5) & 511;

    unsigned short h[8], l[8];
    if (tt < T1) {
        float4 f0 = *(const float4*)(g_y1t + base);
        float4 f1 = *(const float4*)(g_y1t + base + 4);
        float vv[8] = { f0.x, f0.y, f0.z, f0.w, f1.x, f1.y, f1.z, f1.w };
#pragma unroll
        for (int i = 0; i < 8; i++) {
            float v = fmaf(vv[i], scs[c0 + i], shs[c0 + i]);
            v = v > 0.f ? v : 0.f;
            split_bf16(v, h[i], l[i]);
        }
    } else {
#pragma unroll
        for (int i = 0; i < 8; i++) { h[i] = 0; l[i] = 0; }
    }
    uint4 ph = make_uint4(((uint32_t)h[1] << 16) | h[0], ((uint32_t)h[3] << 16) | h[2],
                          ((uint32_t)h[5] << 16) | h[4], ((uint32_t)h[7] << 16) | h[6]);
    uint4 pl = make_uint4(((uint32_t)l[1] << 16) | l[0], ((uint32_t)l[3] << 16) | l[2],
                          ((uint32_t)l[5] << 16) | l[4], ((uint32_t)l[7] << 16) | l[6]);
    *(uint4*)(g_zth + base) = ph;
    *(uint4*)(g_ztl + base) = pl;
}

// ---------------- conv2 via single K=800 GEMM, one block per batch ----------------
// grid 512, 192 threads (6 warps x m16 = 96 rows >= T2). Full 512-row z slab staged once.
// Dynamic smem layout (bytes):
//   [0, 32768)        zah  512x32 ushort  (2048 uint4)
//   [32768, 65536)    zal
//   [65536, 70656)    wbh  32x80 ushort chunk
//   [70656, 75776)    wbl
//   [75776, 76032)    s_sum/s_sq
#define C2_SMEM 76032
__global__ void __launch_bounds__(192) conv2_mma_kernel() {
    extern __shared__ __align__(16) char sm[];
    unsigned short* zah = (unsigned short*)(sm);
    unsigned short* zal = (unsigned short*)(sm + 32768);
    unsigned short* wbh = (unsigned short*)(sm + 65536);
    unsigned short* wbl = (unsigned short*)(sm + 70656);
    float* s_sum = (float*)(sm + 75776);
    float* s_sq  = s_sum + 32;

    const int tid  = threadIdx.x;
    const int w    = tid >> 5;      // 0..5
    const int lane = tid & 31;
    const int g    = lane >> 2;
    const int q    = lane & 3;
    const int b    = blockIdx.x;

    if (tid < 32) { s_sum[tid] = 0.f; s_sq[tid] = 0.f; }

    // stage full z slab (512 rows x 32 ch = 32768 B = 2048 uint4 per array) via cp.async
    {
        const char* szh = (const char*)(g_zth + b * 512 * 32);
        const char* szl = (const char*)(g_ztl + b * 512 * 32);
        uint32_t dzh = smem_u32(zah);
        uint32_t dzl = smem_u32(zal);
        for (int i = tid; i < 2048; i += 192) {
            cpa16(dzh + i * 16, szh + i * 16);
            cpa16(dzl + i * 16, szl + i * 16);
        }
        CP_COMMIT();
    }

    float acc[4][4] = {};
    const uint32_t* ZAH = (const uint32_t*)zah;
    const uint32_t* ZAL = (const uint32_t*)zal;
    const uint32_t* WBH = (const uint32_t*)wbh;
    const uint32_t* WBL = (const uint32_t*)wbl;

    const int mrow  = w * 16 + g;          // 0..87; +8 -> up to 95; z row max 5*95+24 = 499 < 512
    const int base0 = mrow * 80 + q;       // A row stride = 160 bf16 = 80 uint32
    const int base1 = (mrow + 8) * 80 + q;

    for (int ch = 0; ch < 10; ch++) {
        __syncthreads();
        {
            const char* swh = (const char*)(g_w2h) + ch * 160;  // row stride 1600 B
            const char* swl = (const char*)(g_w2l) + ch * 160;
            uint32_t dwh = smem_u32(wbh);
            uint32_t dwl = smem_u32(wbl);
            for (int i = tid; i < 320; i += 192) {
                int oc = i / 10, j = i - oc * 10;
                cpa16(dwh + (oc * 10 + j) * 16, swh + oc * 1600 + j * 16);
                cpa16(dwl + (oc * 10 + j) * 16, swl + oc * 1600 + j * 16);
            }
            CP_COMMIT();
            CP_WAIT0();   // also covers the z slab on first iteration
        }
        __syncthreads();

#pragma unroll
        for (int ksl = 0; ksl < 5; ksl++) {
            const int ao = 8 * (ch * 5 + ksl);
            uint32_t ah[4], al[4];
            ah[0] = ZAH[base0 + ao];     ah[1] = ZAH[base1 + ao];
            ah[2] = ZAH[base0 + ao + 4]; ah[3] = ZAH[base1 + ao + 4];
            al[0] = ZAL[base0 + ao];     al[1] = ZAL[base1 + ao];
            al[2] = ZAL[base0 + ao + 4]; al[3] = ZAL[base1 + ao + 4];
#pragma unroll
            for (int nt = 0; nt < 4; nt++) {
                int bi = (nt * 8 + g) * 40 + 8 * ksl + q;
                uint32_t bhf[2] = { WBH[bi], WBH[bi + 4] };
                uint32_t blf[2] = { WBL[bi], WBL[bi + 4] };
                MMA16(acc[nt], ah, bhf);
                MMA16(acc[nt], ah, blf);
                MMA16(acc[nt], al, bhf);
            }
        }
    }

    float psum[4][2] = {}, psq[4][2] = {};
#pragma unroll
    for (int rr = 0; rr < 2; rr++) {
        int t = mrow + rr * 8;
        if (t < T2) {
#pragma unroll
            for (int nt = 0; nt < 4; nt++) {
#pragma unroll
                for (int j = 0; j < 2; j++) {
                    float v = acc[nt][rr * 2 + j];
                    int oc = nt * 8 + q * 2 + j;
                    g_y2t[(b * T2 + t) * NF + oc] = v;
                    psum[nt][j] += v;
                    psq[nt][j]  += v * v;
                }
            }
        }
    }
#pragma unroll
    for (int nt = 0; nt < 4; nt++)
#pragma unroll
        for (int j = 0; j < 2; j++) {
            atomicAdd(&s_sum[nt * 8 + q * 2 + j], psum[nt][j]);
            atomicAdd(&s_sq [nt * 8 + q * 2 + j], psq[nt][j]);
        }
    __syncthreads();
    if (tid < 32) {
        atomicAdd(&g_stats2[tid],      s_sum[tid]);
        atomicAdd(&g_stats2[32 + tid], s_sq[tid]);
    }
}

// ---------------- projection + layernorm (BN2 finalize folded in) ----------------
__global__ void projln_kernel(const float* __restrict__ pw,
                              const float* __restrict__ pb,
                              const float* __restrict__ lng,
                              const float* __restrict__ lnb,
                              const float* __restrict__ bn2g,
                              const float* __restrict__ bn2b) {
    __shared__ float pws[32 * 33];
    const int tid = threadIdx.x;
    for (int idx = tid; idx < 1024; idx += blockDim.x)
        pws[(idx & 31) * 33 + (idx >> 5)] = pw[idx];
    __syncthreads();

    const int lane   = tid & 31;
    const int warpId = (blockIdx.x * blockDim.x + tid) >> 5;
    const int nw     = (gridDim.x * blockDim.x) >> 5;

    const float nInv = 1.f / (float)(B * T2);
    const float mean = g_stats2[lane] * nInv;
    const float var  = g_stats2[32 + lane] * nInv - mean * mean;
    const float s2   = bn2g[lane] * rsqrtf(var + EPSV);
    const float sh2  = bn2b[lane] - mean * s2;

    const float pbv = pb[lane];
    const float lg  = lng[lane], lb = lnb[lane];

    for (int task = warpId; task < B * T2; task += nw) {
        float v = g_y2t[task * NF + lane];
        v = fmaf(v, s2, sh2);
        v = v > 0.f ? v : 0.f;

        float a = pbv;
#pragma unroll
        for (int f = 0; f < 32; f++)
            a = fmaf(__shfl_sync(0xffffffffu, v, f), pws[f * 33 + lane], a);

        float s = a;
#pragma unroll
        for (int off = 16; off > 0; off >>= 1) s += __shfl_xor_sync(0xffffffffu, s, off);
        float mean2 = s * (1.f / 32.f);
        float d = a - mean2;
        float qq = d * d;
#pragma unroll
        for (int off = 16; off > 0; off >>= 1) qq += __shfl_xor_sync(0xffffffffu, qq, off);
        float var2 = qq * (1.f / 32.f);
        g_xt[task * LAT + lane] = fmaf(d * rsqrtf(var2 + EPSV), lg, lb);
    }
}

// ---------------- PLRNN scan + pool + output projection ----------------
__global__ void recur_kernel(const float* __restrict__ Ain,
                             const float* __restrict__ Win,
                             const float* __restrict__ hbin,
                             const float* __restrict__ owin,
                             const float* __restrict__ obin,
                             float* __restrict__ out) {
    __shared__ float As[32 * 33];
    __shared__ float Ws[32 * 65];
    __shared__ float ows[32 * 33];
    __shared__ float hbs[64];

    const int tid = threadIdx.x;
    for (int idx = tid; idx < 1024; idx += 128) {
        As[(idx >> 5) * 33 + (idx & 31)]  = Ain[idx];
        ows[(idx >> 5) * 33 + (idx & 31)] = owin[idx];
    }
    for (int idx = tid; idx < 2048; idx += 128)
        Ws[(idx >> 6) * 65 + (idx & 63)] = Win[idx];
    if (tid < 64) hbs[tid] = hbin[tid];
    __syncthreads();

    const int lane = tid & 31;
    const int b    = blockIdx.x * 4 + (tid >> 5);

    float h = 0.f, sum = 0.f;
    const float* xrow = g_xt + b * T2 * LAT + lane;

    for (int t = 0; t < T2; t++) {
        float xv = xrow[t * LAT];
        float lin = 0.f;
        float p0 = hbs[lane];
        float p1 = hbs[32 + lane];
#pragma unroll
        for (int m = 0; m < 32; m++) {
            float hm = __shfl_sync(0xffffffffu, h, m);
            lin = fmaf(As[lane * 33 + m],      hm, lin);
            p0  = fmaf(Ws[m * 65 + lane],      hm, p0);
            p1  = fmaf(Ws[m * 65 + 32 + lane], hm, p1);
        }
        float r0 = fmaxf(p0, 0.f);
        float r1 = fmaxf(p1, 0.f);
        float nl = 0.f;
#pragma unroll
        for (int j = 0; j < 32; j++)
            nl = fmaf(__shfl_sync(0xffffffffu, r0, j), Ws[lane * 65 + j], nl);
#pragma unroll
        for (int j = 0; j < 32; j++)
            nl = fmaf(__shfl_sync(0xffffffffu, r1, j), Ws[lane * 65 + 32 + j], nl);

        h = lin + nl + xv;
        sum += h;
    }

    float pooled = sum * (1.f / (float)T2);
    float o = obin[lane];
#pragma unroll
    for (int m = 0; m < 32; m++)
        o = fmaf(ows[lane * 33 + m], __shfl_sync(0xffffffffu, pooled, m), o);
    out[b * 32 + lane] = o;
}

// ---------------- launcher ----------------
extern "C" void kernel_launch(void* const* d_in, const int* in_sizes, int n_in,
                              void* d_out, int out_size) {
    const float* x       = (const float*)d_in[0];
    const float* conv1_w = (const float*)d_in[1];
    const float* bn1_g   = (const float*)d_in[3];
    const float* bn1_b   = (const float*)d_in[4];
    const float* conv2_w = (const float*)d_in[5];
    const float* bn2_g   = (const float*)d_in[7];
    const float* bn2_b   = (const float*)d_in[8];
    const float* proj_w  = (const float*)d_in[9];
    const float* proj_b  = (const float*)d_in[10];
    const float* ln_g    = (const float*)d_in[11];
    const float* ln_b    = (const float*)d_in[12];
    const float* A       = (const float*)d_in[13];
    const float* W       = (const float*)d_in[14];
    const float* h_bias  = (const float*)d_in[15];
    const float* out_w   = (const float*)d_in[16];
    const float* out_b   = (const float*)d_in[17];
    float* out = (float*)d_out;

    cudaFuncSetAttribute(conv2_mma_kernel,
                         cudaFuncAttributeMaxDynamicSharedMemorySize, C2_SMEM);

    prep_all_kernel<<<4096, 256>>>(x, conv1_w, conv2_w);
    conv1_mma_kernel<<<dim3(4, B), 128>>>();
    ztprep_kernel<<<4096, 256>>>(bn1_g, bn1_b);
    conv2_mma_kernel<<<512, 192, C2_SMEM>>>();
    projln_kernel<<<512, 256>>>(proj_w, proj_b, ln_g, ln_b, bn2_g, bn2_b);
    recur_kernel<<<128, 128>>>(A, W, h_bias, out_w, out_b, out);
}

// round 16
// speedup vs baseline: 2.6232x; 1.0780x over previous
#include <cuda_runtime.h>
#include <cuda_bf16.h>
#include <cstdint>

// ---------------- problem constants ----------------
#define B     512
#define C_IN  12
#define T_IN  5000
#define T1    496      // (5000-50)/10+1
#define T2    95       // (496-25)/5+1
#define NF    32
#define LAT   32
#define HID   64
#define EPSV  1e-5f
#define NX    (B * C_IN * T_IN)

// ---------------- scratch (static device memory; no allocation) ----------------
__device__ float g_y1t[B * 512 * 32];      // conv1 raw output T-MAJOR [b][t][oc] (rows >= T1 garbage)
__device__ float g_y2t[B * T2 * NF];       // conv2 raw output TRANSPOSED [b][t][f]
__device__ float g_xt[B * T2 * LAT];       // post proj+LN [b][t][l]
__device__ float g_stats1[64];             // sum[32], sumsq[32]
__device__ float g_stats2[64];

// pre-split bf16 operands
__device__ unsigned short g_xh[NX + 512], g_xl[NX + 512];   // x hi/lo (+pad, zeroed)
__device__ unsigned short g_w1h[C_IN * 32 * 56], g_w1l[C_IN * 32 * 56]; // [c][oc][56], k>=50 zero
__device__ unsigned short g_zth[B * 512 * 32], g_ztl[B * 512 * 32];     // z transposed [b][tt][c] (tt>=496 zero)
__device__ unsigned short g_w2h[32 * 800], g_w2l[32 * 800];             // [oc][kk], kk=k*32+c

// mma.sync m16n8k16 / m16n8k8, bf16 in, fp32 accum (sm_80+ PTX; HMMA on Blackwell)
#define MMA16(c, a, b) asm volatile( \
    "mma.sync.aligned.m16n8k16.row.col.f32.bf16.bf16.f32 " \
    "{%0,%1,%2,%3}, {%4,%5,%6,%7}, {%8,%9}, {%0,%1,%2,%3};" \
    : "+f"((c)[0]), "+f"((c)[1]), "+f"((c)[2]), "+f"((c)[3]) \
    : "r"((a)[0]), "r"((a)[1]), "r"((a)[2]), "r"((a)[3]), "r"((b)[0]), "r"((b)[1]))

#define MMA8(c, a, b0) asm volatile( \
    "mma.sync.aligned.m16n8k8.row.col.f32.bf16.bf16.f32 " \
    "{%0,%1,%2,%3}, {%4,%5}, {%6}, {%0,%1,%2,%3};" \
    : "+f"((c)[0]), "+f"((c)[1]), "+f"((c)[2]), "+f"((c)[3]) \
    : "r"((a)[0]), "r"((a)[1]), "r"((b0)))

__device__ __forceinline__ void split_bf16(float v, unsigned short& h, unsigned short& l) {
    __nv_bfloat16 hb = __float2bfloat16(v);
    h = __bfloat16_as_ushort(hb);
    l = __bfloat16_as_ushort(__float2bfloat16(v - __bfloat162float(hb)));
}

__device__ __forceinline__ uint32_t smem_u32(const void* p) {
    uint32_t a;
    asm("{ .reg .u64 t; cvta.to.shared.u64 t, %1; cvt.u32.u64 %0, t; }" : "=r"(a) : "l"(p));
    return a;
}
__device__ __forceinline__ void cpa16(uint32_t d, const void* s) {
    asm volatile("cp.async.ca.shared.global [%0], [%1], 16;" :: "r"(d), "l"(s));
}
#define CP_COMMIT() asm volatile("cp.async.commit_group;" ::: "memory")
#define CP_WAIT0()  asm volatile("cp.async.wait_group 0;" ::: "memory")
#define CP_WAIT1()  asm volatile("cp.async.wait_group 1;" ::: "memory")

// ---------------- prep (merged): zero stats + split w1, w2, x ----------------
__global__ void prep_all_kernel(const float* __restrict__ x,
                                const float* __restrict__ w1,
                                const float* __restrict__ w2) {
    const int gid = blockIdx.x * blockDim.x + threadIdx.x;
    const int nth = gridDim.x * blockDim.x;

    if (gid < 64) { g_stats1[gid] = 0.f; g_stats2[gid] = 0.f; }
    if (gid < 512) { g_xh[NX + gid] = 0; g_xl[NX + gid] = 0; }

    for (int i = gid; i < C_IN * 32 * 56; i += nth) {
        int c = i / 1792, r = i - c * 1792;
        int oc = r / 56, k = r - oc * 56;
        float v = (k < 50) ? w1[oc * 600 + c * 50 + k] : 0.f;
        split_bf16(v, g_w1h[i], g_w1l[i]);
    }
    for (int i = gid; i < 32 * 800; i += nth) {
        int oc = i / 800, r = i - oc * 800;
        int k = r >> 5, c = r & 31;
        split_bf16(w2[oc * 800 + c * 25 + k], g_w2h[i], g_w2l[i]);
    }
    for (int i = gid; i < NX / 4; i += nth) {
        int i4 = i * 4;
        float4 v = *(const float4*)(x + i4);
        unsigned short h0, l0, h1, l1, h2, l2, h3, l3;
        split_bf16(v.x, h0, l0); split_bf16(v.y, h1, l1);
        split_bf16(v.z, h2, l2); split_bf16(v.w, h3, l3);
        *(uint2*)(g_xh + i4) = make_uint2(((uint32_t)h1 << 16) | h0, ((uint32_t)h3 << 16) | h2);
        *(uint2*)(g_xl + i4) = make_uint2(((uint32_t)l1 << 16) | l0, ((uint32_t)l3 << 16) | l2);
    }
}

// ---------------- conv1 via mma.sync (pre-split bf16, cp.async double-buffer) ----------------
// grid (4, 512): x = t-tile of 128 outputs, y = batch. 128 threads (4 warps).
__global__ void __launch_bounds__(128) conv1_mma_kernel() {
    __shared__ __align__(16) unsigned short xhS[2][1344], xlS[2][1344];
    __shared__ __align__(16) unsigned short bhS[2][1792], blS[2][1792];
    __shared__ float s_sum[32], s_sq[32];

    const int tid  = threadIdx.x;
    const int w    = tid >> 5;
    const int lane = tid & 31;
    const int g    = lane >> 2;
    const int q    = lane & 3;
    const int b    = blockIdx.y;
    const int t0   = blockIdx.x * 128;

    if (tid < 32) { s_sum[tid] = 0.f; s_sq[tid] = 0.f; }

    float acc[2][4][4] = {};

    auto prefetch = [&](int c, int buf) {
        const char* sxh = (const char*)(g_xh + (b * C_IN + c) * T_IN + t0 * 10);
        const char* sxl = (const char*)(g_xl + (b * C_IN + c) * T_IN + t0 * 10);
        uint32_t dxh = smem_u32(&xhS[buf][0]);
        uint32_t dxl = smem_u32(&xlS[buf][0]);
        for (int i = tid; i < 167; i += 128) {
            cpa16(dxh + i * 16, sxh + i * 16);
            cpa16(dxl + i * 16, sxl + i * 16);
        }
        const char* swh = (const char*)(g_w1h + c * 1792);
        const char* swl = (const char*)(g_w1l + c * 1792);
        uint32_t dbh = smem_u32(&bhS[buf][0]);
        uint32_t dbl = smem_u32(&blS[buf][0]);
        for (int i = tid; i < 224; i += 128) {
            cpa16(dbh + i * 16, swh + i * 16);
            cpa16(dbl + i * 16, swl + i * 16);
        }
        CP_COMMIT();
    };

    prefetch(0, 0);

    for (int c = 0; c < C_IN; c++) {
        const int buf = c & 1;
        __syncthreads();
        if (c + 1 < C_IN) { prefetch(c + 1, buf ^ 1); CP_WAIT1(); }
        else              { CP_WAIT0(); }
        __syncthreads();

        const uint32_t* XH = (const uint32_t*)xhS[buf];
        const uint32_t* XL = (const uint32_t*)xlS[buf];
        const uint32_t* BH = (const uint32_t*)bhS[buf];
        const uint32_t* BL = (const uint32_t*)blS[buf];

        const int m0 = w * 32 + g;
#pragma unroll
        for (int ks = 0; ks < 3; ks++) {
            const int ao = q + ks * 8;
            uint32_t ah[2][4], al[2][4];
#pragma unroll
            for (int mt = 0; mt < 2; mt++) {
                int i0 = 5 * (m0 + mt * 16) + ao;
                ah[mt][0] = XH[i0];      ah[mt][1] = XH[i0 + 40];
                ah[mt][2] = XH[i0 + 4];  ah[mt][3] = XH[i0 + 44];
                al[mt][0] = XL[i0];      al[mt][1] = XL[i0 + 40];
                al[mt][2] = XL[i0 + 4];  al[mt][3] = XL[i0 + 44];
            }
#pragma unroll
            for (int nt = 0; nt < 4; nt++) {
                int bi = 28 * (nt * 8 + g) + q + ks * 8;
                uint32_t bhf[2] = { BH[bi], BH[bi + 4] };
                uint32_t blf[2] = { BL[bi], BL[bi + 4] };
#pragma unroll
                for (int mt = 0; mt < 2; mt++) {
                    MMA16(acc[mt][nt], ah[mt], bhf);
                    MMA16(acc[mt][nt], ah[mt], blf);
                    MMA16(acc[mt][nt], al[mt], bhf);
                }
            }
        }
        {
            const int ao = 24 + q;
            uint32_t ah[2][2], al[2][2];
#pragma unroll
            for (int mt = 0; mt < 2; mt++) {
                int i0 = 5 * (m0 + mt * 16) + ao;
                ah[mt][0] = XH[i0]; ah[mt][1] = XH[i0 + 40];
                al[mt][0] = XL[i0]; al[mt][1] = XL[i0 + 40];
            }
#pragma unroll
            for (int nt = 0; nt < 4; nt++) {
                int bi = 28 * (nt * 8 + g) + 24 + q;
                uint32_t b0h = BH[bi], b0l = BL[bi];
#pragma unroll
                for (int mt = 0; mt < 2; mt++) {
                    MMA8(acc[mt][nt], ah[mt], b0h);
                    MMA8(acc[mt][nt], ah[mt], b0l);
                    MMA8(acc[mt][nt], al[mt], b0h);
                }
            }
        }
    }

    float psum[4][2] = {}, psq[4][2] = {};
#pragma unroll
    for (int mt = 0; mt < 2; mt++) {
#pragma unroll
        for (int rr = 0; rr < 2; rr++) {
            int t = t0 + w * 32 + mt * 16 + g + rr * 8;
            if (t < T1) {
                float* drow = g_y1t + (b * 512 + t) * 32;
#pragma unroll
                for (int nt = 0; nt < 4; nt++) {
#pragma unroll
                    for (int j = 0; j < 2; j++) {
                        float v = acc[mt][nt][rr * 2 + j];
                        drow[nt * 8 + q * 2 + j] = v;
                        psum[nt][j] += v;
                        psq[nt][j]  += v * v;
                    }
                }
            }
        }
    }
#pragma unroll
    for (int nt = 0; nt < 4; nt++)
#pragma unroll
        for (int j = 0; j < 2; j++) {
            atomicAdd(&s_sum[nt * 8 + q * 2 + j], psum[nt][j]);
            atomicAdd(&s_sq [nt * 8 + q * 2 + j], psq[nt][j]);
        }
    __syncthreads();
    if (tid < 32) {
        atomicAdd(&g_stats1[tid],      s_sum[tid]);
        atomicAdd(&g_stats1[32 + tid], s_sq[tid]);
    }
}

// ---------------- zt prep (streaming): z = relu(bn1(y1t)) -> bf16 hi/lo, same layout ----------------
__global__ void __launch_bounds__(256) ztprep_kernel(const float* __restrict__ bn1g,
                                                     const float* __restrict__ bn1b) {
    __shared__ float scs[32], shs[32];
    const int tid = threadIdx.x;
    if (tid < 32) {
        const float nInv = 1.f / (float)(B * T1);
        const float mean = g_stats1[tid] * nInv;
        const float var  = g_stats1[32 + tid] * nInv - mean * mean;
        const float sc   = bn1g[tid] * rsqrtf(var + EPSV);
        scs[tid] = sc;
        shs[tid] = bn1b[tid] - mean * sc;
    }
    __syncthreads();

    const int idx8 = blockIdx.x * 256 + tid;
    const int base = idx8 * 8;
    const int c0   = base & 31;
    const int tt   = (base >> 5) & 511;

    unsigned short h[8], l[8];
    if (tt < T1) {
        float4 f0 = *(const float4*)(g_y1t + base);
        float4 f1 = *(const float4*)(g_y1t + base + 4);
        float vv[8] = { f0.x, f0.y, f0.z, f0.w, f1.x, f1.y, f1.z, f1.w };
#pragma unroll
        for (int i = 0; i < 8; i++) {
            float v = fmaf(vv[i], scs[c0 + i], shs[c0 + i]);
            v = v > 0.f ? v : 0.f;
            split_bf16(v, h[i], l[i]);
        }
    } else {
#pragma unroll
        for (int i = 0; i < 8; i++) { h[i] = 0; l[i] = 0; }
    }
    uint4 ph = make_uint4(((uint32_t)h[1] << 16) | h[0], ((uint32_t)h[3] << 16) | h[2],
                          ((uint32_t)h[5] << 16) | h[4], ((uint32_t)h[7] << 16) | h[6]);
    uint4 pl = make_uint4(((uint32_t)l[1] << 16) | l[0], ((uint32_t)l[3] << 16) | l[2],
                          ((uint32_t)l[5] << 16) | l[4], ((uint32_t)l[7] << 16) | l[6]);
    *(uint4*)(g_zth + base) = ph;
    *(uint4*)(g_ztl + base) = pl;
}

// ---------------- conv2 via single K=800 GEMM, one block per batch ----------------
// grid 512, 192 threads (6 warps x m16 = 96 rows >= T2).
// Bank-conflict-free smem: zt rows padded 32->40 ushort (GEMM-row stride 100 words = g*4 mod 32),
// weight rows padded 80->88 ushort (stride 44 words = g*12 mod 32). Weight chunks double-buffered.
// smem layout (bytes):
//   [0, 40960)          zah  512 rows x 80 B
//   [40960, 81920)      zal
//   [81920, 93184)      wb buf0: h at +0 (32x176), l at +5632
//   [93184, 104448)     wb buf1
//   [104448, 104704)    s_sum/s_sq
#define C2_SMEM 104704
__global__ void __launch_bounds__(192) conv2_mma_kernel() {
    extern __shared__ __align__(16) char sm[];
    unsigned short* zah = (unsigned short*)(sm);
    unsigned short* zal = (unsigned short*)(sm + 40960);
    float* s_sum = (float*)(sm + 104448);
    float* s_sq  = s_sum + 32;

    const int tid  = threadIdx.x;
    const int w    = tid >> 5;      // 0..5
    const int lane = tid & 31;
    const int g    = lane >> 2;
    const int q    = lane & 3;
    const int b    = blockIdx.x;

    if (tid < 32) { s_sum[tid] = 0.f; s_sq[tid] = 0.f; }

    // stage weight chunk ch into buffer buf (32 oc x 80 ushort data, padded row 88)
    auto stageW = [&](int ch, int buf) {
        const char* swh = (const char*)(g_w2h) + ch * 160;   // row stride 1600 B
        const char* swl = (const char*)(g_w2l) + ch * 160;
        uint32_t dwh = smem_u32(sm + 81920 + buf * 11264);
        uint32_t dwl = dwh + 5632;
        for (int i = tid; i < 320; i += 192) {
            int oc = i / 10, j = i - oc * 10;
            cpa16(dwh + oc * 176 + j * 16, swh + oc * 1600 + j * 16);
            cpa16(dwl + oc * 176 + j * 16, swl + oc * 1600 + j * 16);
        }
        CP_COMMIT();
    };

    // stage z slab: 512 zt rows, 64 B data each -> padded 80 B rows
    {
        const char* szh = (const char*)(g_zth + b * 512 * 32);
        const char* szl = (const char*)(g_ztl + b * 512 * 32);
        uint32_t dzh = smem_u32(zah);
        uint32_t dzl = smem_u32(zal);
        for (int i = tid; i < 2048; i += 192) {
            int r = i >> 2, j = i & 3;
            cpa16(dzh + r * 80 + j * 16, szh + r * 64 + j * 16);
            cpa16(dzl + r * 80 + j * 16, szl + r * 64 + j * 16);
        }
    }
    stageW(0, 0);   // group 0 = z slab + W chunk 0

    float acc[4][4] = {};
    const uint32_t* ZAH = (const uint32_t*)zah;
    const uint32_t* ZAL = (const uint32_t*)zal;

    const int mrow  = w * 16 + g;          // 0..87; +8 -> up to 95; zt row max 5*95+24 = 499 < 512
    const int base0 = mrow * 100 + q;      // GEMM-row stride = 5 zt rows x 20 words = 100 words
    const int base1 = (mrow + 8) * 100 + q;

    for (int ch = 0; ch < 10; ch++) {
        const int buf = ch & 1;
        if (ch + 1 < 10) { stageW(ch + 1, buf ^ 1); CP_WAIT1(); }
        else             { CP_WAIT0(); }
        __syncthreads();

        const uint32_t* WBH = (const uint32_t*)(sm + 81920 + buf * 11264);
        const uint32_t* WBL = (const uint32_t*)(sm + 81920 + buf * 11264 + 5632);

#pragma unroll
        for (int ksl = 0; ksl < 5; ksl++) {
            const int s  = ch * 5 + ksl;
            const int ao = (s >> 1) * 20 + (s & 1) * 8;   // padded word offset within GEMM row
            uint32_t ah[4], al[4];
            ah[0] = ZAH[base0 + ao];     ah[1] = ZAH[base1 + ao];
            ah[2] = ZAH[base0 + ao + 4]; ah[3] = ZAH[base1 + ao + 4];
            al[0] = ZAL[base0 + ao];     al[1] = ZAL[base1 + ao];
            al[2] = ZAL[base0 + ao + 4]; al[3] = ZAL[base1 + ao + 4];
#pragma unroll
            for (int nt = 0; nt < 4; nt++) {
                int bi = (nt * 8 + g) * 44 + 8 * ksl + q;   // padded weight row stride 44 words
                uint32_t bhf[2] = { WBH[bi], WBH[bi + 4] };
                uint32_t blf[2] = { WBL[bi], WBL[bi + 4] };
                MMA16(acc[nt], ah, bhf);
                MMA16(acc[nt], ah, blf);
                MMA16(acc[nt], al, bhf);
            }
        }
        __syncthreads();   // all warps done with buf before it is overwritten next iter
    }

    float psum[4][2] = {}, psq[4][2] = {};
#pragma unroll
    for (int rr = 0; rr < 2; rr++) {
        int t = mrow + rr * 8;
        if (t < T2) {
#pragma unroll
            for (int nt = 0; nt < 4; nt++) {
#pragma unroll
                for (int j = 0; j < 2; j++) {
                    float v = acc[nt][rr * 2 + j];
                    int oc = nt * 8 + q * 2 + j;
                    g_y2t[(b * T2 + t) * NF + oc] = v;
                    psum[nt][j] += v;
                    psq[nt][j]  += v * v;
                }
            }
        }
    }
#pragma unroll
    for (int nt = 0; nt < 4; nt++)
#pragma unroll
        for (int j = 0; j < 2; j++) {
            atomicAdd(&s_sum[nt * 8 + q * 2 + j], psum[nt][j]);
            atomicAdd(&s_sq [nt * 8 + q * 2 + j], psq[nt][j]);
        }
    __syncthreads();
    if (tid < 32) {
        atomicAdd(&g_stats2[tid],      s_sum[tid]);
        atomicAdd(&g_stats2[32 + tid], s_sq[tid]);
    }
}

// ---------------- projection + layernorm (BN2 finalize folded in) ----------------
__global__ void projln_kernel(const float* __restrict__ pw,
                              const float* __restrict__ pb,
                              const float* __restrict__ lng,
                              const float* __restrict__ lnb,
                              const float* __restrict__ bn2g,
                              const float* __restrict__ bn2b) {
    __shared__ float pws[32 * 33];
    const int tid = threadIdx.x;
    for (int idx = tid; idx < 1024; idx += blockDim.x)
        pws[(idx & 31) * 33 + (idx >> 5)] = pw[idx];
    __syncthreads();

    const int lane   = tid & 31;
    const int warpId = (blockIdx.x * blockDim.x + tid) >> 5;
    const int nw     = (gridDim.x * blockDim.x) >> 5;

    const float nInv = 1.f / (float)(B * T2);
    const float mean = g_stats2[lane] * nInv;
    const float var  = g_stats2[32 + lane] * nInv - mean * mean;
    const float s2   = bn2g[lane] * rsqrtf(var + EPSV);
    const float sh2  = bn2b[lane] - mean * s2;

    const float pbv = pb[lane];
    const float lg  = lng[lane], lb = lnb[lane];

    for (int task = warpId; task < B * T2; task += nw) {
        float v = g_y2t[task * NF + lane];
        v = fmaf(v, s2, sh2);
        v = v > 0.f ? v : 0.f;

        float a = pbv;
#pragma unroll
        for (int f = 0; f < 32; f++)
            a = fmaf(__shfl_sync(0xffffffffu, v, f), pws[f * 33 + lane], a);

        float s = a;
#pragma unroll
        for (int off = 16; off > 0; off >>= 1) s += __shfl_xor_sync(0xffffffffu, s, off);
        float mean2 = s * (1.f / 32.f);
        float d = a - mean2;
        float qq = d * d;
#pragma unroll
        for (int off = 16; off > 0; off >>= 1) qq += __shfl_xor_sync(0xffffffffu, qq, off);
        float var2 = qq * (1.f / 32.f);
        g_xt[task * LAT + lane] = fmaf(d * rsqrtf(var2 + EPSV), lg, lb);
    }
}

// ---------------- PLRNN scan + pool + output projection ----------------
__global__ void recur_kernel(const float* __restrict__ Ain,
                             const float* __restrict__ Win,
                             const float* __restrict__ hbin,
                             const float* __restrict__ owin,
                             const float* __restrict__ obin,
                             float* __restrict__ out) {
    __shared__ float As[32 * 33];
    __shared__ float Ws[32 * 65];
    __shared__ float ows[32 * 33];
    __shared__ float hbs[64];

    const int tid = threadIdx.x;
    for (int idx = tid; idx < 1024; idx += 128) {
        As[(idx >> 5) * 33 + (idx & 31)]  = Ain[idx];
        ows[(idx >> 5) * 33 + (idx & 31)] = owin[idx];
    }
    for (int idx = tid; idx < 2048; idx += 128)
        Ws[(idx >> 6) * 65 + (idx & 63)] = Win[idx];
    if (tid < 64) hbs[tid] = hbin[tid];
    __syncthreads();

    const int lane = tid & 31;
    const int b    = blockIdx.x * 4 + (tid >> 5);

    float h = 0.f, sum = 0.f;
    const float* xrow = g_xt + b * T2 * LAT + lane;

    for (int t = 0; t < T2; t++) {
        float xv = xrow[t * LAT];
        float lin = 0.f;
        float p0 = hbs[lane];
        float p1 = hbs[32 + lane];
#pragma unroll
        for (int m = 0; m < 32; m++) {
            float hm = __shfl_sync(0xffffffffu, h, m);
            lin = fmaf(As[lane * 33 + m],      hm, lin);
            p0  = fmaf(Ws[m * 65 + lane],      hm, p0);
            p1  = fmaf(Ws[m * 65 + 32 + lane], hm, p1);
        }
        float r0 = fmaxf(p0, 0.f);
        float r1 = fmaxf(p1, 0.f);
        float nl = 0.f;
#pragma unroll
        for (int j = 0; j < 32; j++)
            nl = fmaf(__shfl_sync(0xffffffffu, r0, j), Ws[lane * 65 + j], nl);
#pragma unroll
        for (int j = 0; j < 32; j++)
            nl = fmaf(__shfl_sync(0xffffffffu, r1, j), Ws[lane * 65 + 32 + j], nl);

        h = lin + nl + xv;
        sum += h;
    }

    float pooled = sum * (1.f / (float)T2);
    float o = obin[lane];
#pragma unroll
    for (int m = 0; m < 32; m++)
        o = fmaf(ows[lane * 33 + m], __shfl_sync(0xffffffffu, pooled, m), o);
    out[b * 32 + lane] = o;
}

// ---------------- launcher ----------------
extern "C" void kernel_launch(void* const* d_in, const int* in_sizes, int n_in,
                              void* d_out, int out_size) {
    const float* x       = (const float*)d_in[0];
    const float* conv1_w = (const float*)d_in[1];
    const float* bn1_g   = (const float*)d_in[3];
    const float* bn1_b   = (const float*)d_in[4];
    const float* conv2_w = (const float*)d_in[5];
    const float* bn2_g   = (const float*)d_in[7];
    const float* bn2_b   = (const float*)d_in[8];
    const float* proj_w  = (const float*)d_in[9];
    const float* proj_b  = (const float*)d_in[10];
    const float* ln_g    = (const float*)d_in[11];
    const float* ln_b    = (const float*)d_in[12];
    const float* A       = (const float*)d_in[13];
    const float* W       = (const float*)d_in[14];
    const float* h_bias  = (const float*)d_in[15];
    const float* out_w   = (const float*)d_in[16];
    const float* out_b   = (const float*)d_in[17];
    float* out = (float*)d_out;

    cudaFuncSetAttribute(conv2_mma_kernel,
                         cudaFuncAttributeMaxDynamicSharedMemorySize, C2_SMEM);

    prep_all_kernel<<<4096, 256>>>(x, conv1_w, conv2_w);
    conv1_mma_kernel<<<dim3(4, B), 128>>>();
    ztprep_kernel<<<4096, 256>>>(bn1_g, bn1_b);
    conv2_mma_kernel<<<512, 192, C2_SMEM>>>();
    projln_kernel<<<512, 256>>>(proj_w, proj_b, ln_g, ln_b, bn2_g, bn2_b);
    recur_kernel<<<128, 128>>>(A, W, h_bias, out_w, out_b, out);
}